// round 1
// baseline (speedup 1.0000x reference)
#include <cuda_runtime.h>
#include <math.h>

#define NN 256      // nodes
#define TT 30000    // time samples
#define HH 512      // hidden
#define LL 256      // latent
#define EE 32768    // edges
#define SPLITK 15
#define KCHUNK 2000

// ---------------- device scratch (no allocation allowed) ----------------
__device__ float g_B[NN * NN];                 // B = I + A (adjacency counts)
__device__ float g_Ppart[SPLITK * NN * HH];    // split-K partials for X@Ws1a
__device__ float g_P[NN * HH];                 // X@Ws1a
__device__ float g_U1[NN * HH];
__device__ float g_h[NN * HH];
__device__ float g_Q2[NN * LL];
__device__ float g_U2[NN * LL];
__device__ float g_feat[NN * LL];
__device__ float g_Q3[NN * HH];
__device__ float g_U3[NN * HH];
__device__ float g_s[NN * HH];
__device__ float g_Q4[NN];

// ---------------- adjacency build ----------------
__global__ void k_initB() {
    int i = blockIdx.x * blockDim.x + threadIdx.x;   // 65536 threads
    g_B[i] = ((i >> 8) == (i & 255)) ? 1.0f : 0.0f;  // identity (eps=0 GIN)
}

__global__ void k_edges(const int* __restrict__ idx) {
    int e = blockIdx.x * blockDim.x + threadIdx.x;
    if (e < EE) {
        int s = idx[e];        // eeg_idx[0, e]
        int d = idx[EE + e];   // eeg_idx[1, e]
        atomicAdd(&g_B[d * NN + s], 1.0f);  // integer counts: exact, order-independent
    }
}

// ---------------- tiled GEMM: C[M,N] = A[M,K] @ Bm[K,N] ----------------
// EPI: 0 = plain store, 1 = bias + relu, 2 = bias only, 3 = split-K partial store
template <int EPI>
__global__ __launch_bounds__(256)
void gemm_k(const float* __restrict__ A, const float* __restrict__ Bm,
            const float* __restrict__ bias, float* __restrict__ C,
            int M, int N, int K, int kChunk)
{
    __shared__ float As[16 * 64];   // transposed: As[k][m]
    __shared__ float Bs[16 * 64];   // Bs[k][n]

    int tid = threadIdx.x;
    int m0 = blockIdx.y * 64, n0 = blockIdx.x * 64;
    int k0 = blockIdx.z * kChunk;
    int kEnd = k0 + kChunk;
    if (kEnd > K) kEnd = K;

    int arow = tid >> 2;            // 0..63
    int aq   = (tid & 3) << 2;      // 0,4,8,12
    int brow = tid >> 4;            // 0..15
    int bcol = (tid & 15) << 2;     // 0..60

    const float* Aptr = A + (size_t)(m0 + arow) * K + aq;
    const float* Bptr = Bm + (size_t)brow * N + n0 + bcol;

    int ty = tid >> 4, tx = tid & 15;
    float acc[4][4] = {};

    for (int k = k0; k < kEnd; k += 16) {
        float4 av = *(const float4*)(Aptr + k);
        As[(aq + 0) * 64 + arow] = av.x;
        As[(aq + 1) * 64 + arow] = av.y;
        As[(aq + 2) * 64 + arow] = av.z;
        As[(aq + 3) * 64 + arow] = av.w;
        float4 bv = *(const float4*)(Bptr + (size_t)k * N);
        *(float4*)&Bs[brow * 64 + bcol] = bv;
        __syncthreads();

        #pragma unroll
        for (int kk = 0; kk < 16; kk++) {
            float4 a = *(const float4*)&As[kk * 64 + ty * 4];
            float4 b = *(const float4*)&Bs[kk * 64 + tx * 4];
            float ar[4] = {a.x, a.y, a.z, a.w};
            float br[4] = {b.x, b.y, b.z, b.w};
            #pragma unroll
            for (int i = 0; i < 4; i++)
                #pragma unroll
                for (int j = 0; j < 4; j++)
                    acc[i][j] += ar[i] * br[j];
        }
        __syncthreads();
    }

    float* Cp = C;
    if (EPI == 3) Cp = C + (size_t)blockIdx.z * M * N;

    #pragma unroll
    for (int i = 0; i < 4; i++) {
        int m = m0 + ty * 4 + i;
        int n = n0 + tx * 4;
        float4 v = make_float4(acc[i][0], acc[i][1], acc[i][2], acc[i][3]);
        if (EPI == 1) {
            v.x += bias[n + 0]; v.y += bias[n + 1]; v.z += bias[n + 2]; v.w += bias[n + 3];
            v.x = fmaxf(v.x, 0.f); v.y = fmaxf(v.y, 0.f); v.z = fmaxf(v.z, 0.f); v.w = fmaxf(v.w, 0.f);
        } else if (EPI == 2) {
            v.x += bias[n + 0]; v.y += bias[n + 1]; v.z += bias[n + 2]; v.w += bias[n + 3];
        }
        *(float4*)&Cp[(size_t)m * N + n] = v;
    }
}

__global__ void k_reduceP() {
    int i = blockIdx.x * blockDim.x + threadIdx.x;
    if (i < NN * HH) {
        float s = 0.f;
        #pragma unroll
        for (int z = 0; z < SPLITK; z++) s += g_Ppart[z * NN * HH + i];
        g_P[i] = s;
    }
}

// ---------------- N=1 tail: scorer conv2 + sigmoid ----------------
__global__ void k_q4(const float* __restrict__ Wc2a) {
    int warp = (blockIdx.x * blockDim.x + threadIdx.x) >> 5;
    int lane = threadIdx.x & 31;
    if (warp < NN) {
        float s = 0.f;
        for (int i = lane; i < HH; i += 32) s += g_s[warp * HH + i] * Wc2a[i];
        #pragma unroll
        for (int o = 16; o; o >>= 1) s += __shfl_down_sync(0xFFFFFFFFu, s, o);
        if (lane == 0) g_Q4[warp] = s;
    }
}

__global__ void k_region(const float* __restrict__ bc2a, const float* __restrict__ Wc2b,
                         const float* __restrict__ bc2b, float* __restrict__ out) {
    int warp = (blockIdx.x * blockDim.x + threadIdx.x) >> 5;
    int lane = threadIdx.x & 31;
    if (warp < NN) {
        float s = 0.f;
        for (int i = lane; i < NN; i += 32) s += g_B[warp * NN + i] * g_Q4[i];
        #pragma unroll
        for (int o = 16; o; o >>= 1) s += __shfl_down_sync(0xFFFFFFFFu, s, o);
        if (lane == 0) {
            float u = fmaxf(s + bc2a[0], 0.f);
            float sc = u * Wc2b[0] + bc2b[0];
            out[1 + warp] = 1.f / (1.f + expf(-sc));
        }
    }
}

// ---------------- dementia head: sigmoid(feat_flat . Wd + bd) ----------------
__global__ void k_dementia(const float* __restrict__ Wd, const float* __restrict__ bd,
                           float* __restrict__ out) {
    __shared__ float red[32];
    int tid = threadIdx.x;
    float s = 0.f;
    for (int i = tid; i < NN * LL; i += 1024) s += g_feat[i] * Wd[i];
    #pragma unroll
    for (int o = 16; o; o >>= 1) s += __shfl_down_sync(0xFFFFFFFFu, s, o);
    if ((tid & 31) == 0) red[tid >> 5] = s;
    __syncthreads();
    if (tid < 32) {
        float v = red[tid];
        #pragma unroll
        for (int o = 16; o; o >>= 1) v += __shfl_down_sync(0xFFFFFFFFu, v, o);
        if (tid == 0) out[0] = 1.f / (1.f + expf(-(v + bd[0])));
    }
}

// ---------------- launch ----------------
extern "C" void kernel_launch(void* const* d_in, const int* in_sizes, int n_in,
                              void* d_out, int out_size) {
    const float* X    = (const float*)d_in[0];   // eeg_nodes [256, 30000]
    const int*   idx  = (const int*)d_in[1];     // eeg_idx [2, 32768]
    // d_in[2] = eeg_attr (ignored by GINConv)
    const float* Ws1a = (const float*)d_in[3];
    const float* bs1a = (const float*)d_in[4];
    const float* Ws1b = (const float*)d_in[5];
    const float* bs1b = (const float*)d_in[6];
    const float* Ws2a = (const float*)d_in[7];
    const float* bs2a = (const float*)d_in[8];
    const float* Ws2b = (const float*)d_in[9];
    const float* bs2b = (const float*)d_in[10];
    const float* Wc1a = (const float*)d_in[11];
    const float* bc1a = (const float*)d_in[12];
    const float* Wc1b = (const float*)d_in[13];
    const float* bc1b = (const float*)d_in[14];
    const float* Wc2a = (const float*)d_in[15];
    const float* bc2a = (const float*)d_in[16];
    const float* Wc2b = (const float*)d_in[17];
    const float* bc2b = (const float*)d_in[18];
    const float* Wd   = (const float*)d_in[19];
    const float* bd   = (const float*)d_in[20];
    float* out = (float*)d_out;   // [0]=dementia_pred, [1..256]=region_scores

    float *pB, *pPpart, *pP, *pU1, *ph, *pQ2, *pU2, *pfeat, *pQ3, *pU3, *ps;
    cudaGetSymbolAddress((void**)&pB, g_B);
    cudaGetSymbolAddress((void**)&pPpart, g_Ppart);
    cudaGetSymbolAddress((void**)&pP, g_P);
    cudaGetSymbolAddress((void**)&pU1, g_U1);
    cudaGetSymbolAddress((void**)&ph, g_h);
    cudaGetSymbolAddress((void**)&pQ2, g_Q2);
    cudaGetSymbolAddress((void**)&pU2, g_U2);
    cudaGetSymbolAddress((void**)&pfeat, g_feat);
    cudaGetSymbolAddress((void**)&pQ3, g_Q3);
    cudaGetSymbolAddress((void**)&pU3, g_U3);
    cudaGetSymbolAddress((void**)&ps, g_s);

    // Build B = I + A
    k_initB<<<256, 256>>>();
    k_edges<<<(EE + 255) / 256, 256>>>(idx);

    // Big GEMM (split-K, deterministic): P = X @ Ws1a   [256,30000]x[30000,512]
    gemm_k<3><<<dim3(8, 4, SPLITK), 256>>>(X, Ws1a, nullptr, pPpart, NN, HH, TT, KCHUNK);
    k_reduceP<<<(NN * HH + 255) / 256, 256>>>();

    // struct_featurizer conv1: U1 = relu(B@P + bs1a); h = relu(U1@Ws1b + bs1b)
    gemm_k<1><<<dim3(8, 4, 1), 256>>>(pB, pP, bs1a, pU1, NN, HH, NN, NN);
    gemm_k<1><<<dim3(8, 4, 1), 256>>>(pU1, Ws1b, bs1b, ph, NN, HH, HH, HH);

    // conv2: Q2 = h@Ws2a; U2 = relu(B@Q2 + bs2a); feat = U2@Ws2b + bs2b
    gemm_k<0><<<dim3(4, 4, 1), 256>>>(ph, Ws2a, nullptr, pQ2, NN, LL, HH, HH);
    gemm_k<1><<<dim3(4, 4, 1), 256>>>(pB, pQ2, bs2a, pU2, NN, LL, NN, NN);
    gemm_k<2><<<dim3(4, 4, 1), 256>>>(pU2, Ws2b, bs2b, pfeat, NN, LL, LL, LL);

    // scorer conv1: Q3 = feat@Wc1a; U3 = relu(B@Q3 + bc1a); s = relu(U3@Wc1b + bc1b)
    gemm_k<0><<<dim3(8, 4, 1), 256>>>(pfeat, Wc1a, nullptr, pQ3, NN, HH, LL, LL);
    gemm_k<1><<<dim3(8, 4, 1), 256>>>(pB, pQ3, bc1a, pU3, NN, HH, NN, NN);
    gemm_k<1><<<dim3(8, 4, 1), 256>>>(pU3, Wc1b, bc1b, ps, NN, HH, HH, HH);

    // scorer conv2 (N=1) + sigmoid
    k_q4<<<32, 256>>>(Wc2a);
    k_region<<<32, 256>>>(bc2a, Wc2b, bc2b, out);

    // dementia head
    k_dementia<<<1, 1024>>>(Wd, bd, out);
}

// round 2
// speedup vs baseline: 2.1984x; 2.1984x over previous
#include <cuda_runtime.h>
#include <cuda_bf16.h>
#include <math.h>

#define NN 256      // nodes
#define TT 30000    // time samples
#define HH 512      // hidden
#define LL 256      // latent
#define EE 32768    // edges

#define KSTEPS 1875       // 30000 / 16
#define SPLITK 18
#define STEPS_PER 105     // ceil(1875/18); last chunk = 90

#define ASTRIDE 24        // bf16 elems per A smem row (48B, conflict-free ldmatrix)
#define BSTRIDE 136       // bf16 elems per B smem row (272B, conflict-free ldmatrix.trans)

// ---------------- device scratch (no allocation allowed) ----------------
__device__ float g_B[NN * NN];
__device__ float g_Ppart[SPLITK * NN * HH];
__device__ float g_P[NN * HH];
__device__ float g_U1[NN * HH];
__device__ float g_h[NN * HH];
__device__ float g_Q2[NN * LL];
__device__ float g_U2[NN * LL];
__device__ float g_feat[NN * LL];
__device__ float g_Q3[NN * HH];
__device__ float g_U3[NN * HH];
__device__ float g_s[NN * HH];
__device__ float g_Q4[NN];

// ---------------- adjacency build ----------------
__global__ void k_initB() {
    int i = blockIdx.x * blockDim.x + threadIdx.x;
    g_B[i] = ((i >> 8) == (i & 255)) ? 1.0f : 0.0f;
}

__global__ void k_edges(const int* __restrict__ idx) {
    int e = blockIdx.x * blockDim.x + threadIdx.x;
    if (e < EE) {
        int s = idx[e];
        int d = idx[EE + e];
        atomicAdd(&g_B[d * NN + s], 1.0f);
    }
}

// ---------------- tensor-core helpers ----------------
__device__ __forceinline__ void mma_bf16(float* c, const unsigned* a, const unsigned* b) {
    asm volatile(
        "mma.sync.aligned.m16n8k16.row.col.f32.bf16.bf16.f32 "
        "{%0,%1,%2,%3},{%4,%5,%6,%7},{%8,%9},{%0,%1,%2,%3};"
        : "+f"(c[0]), "+f"(c[1]), "+f"(c[2]), "+f"(c[3])
        : "r"(a[0]), "r"(a[1]), "r"(a[2]), "r"(a[3]), "r"(b[0]), "r"(b[1]));
}
__device__ __forceinline__ void ldsm4(unsigned* r, unsigned addr) {
    asm volatile("ldmatrix.sync.aligned.m8n8.x4.shared.b16 {%0,%1,%2,%3},[%4];"
                 : "=r"(r[0]), "=r"(r[1]), "=r"(r[2]), "=r"(r[3]) : "r"(addr));
}
__device__ __forceinline__ void ldsm4t(unsigned* r, unsigned addr) {
    asm volatile("ldmatrix.sync.aligned.m8n8.x4.trans.shared.b16 {%0,%1,%2,%3},[%4];"
                 : "=r"(r[0]), "=r"(r[1]), "=r"(r[2]), "=r"(r[3]) : "r"(addr));
}

// ---------------- big GEMM: Ppart[z] = X_chunk @ W_chunk (bf16-split, 3 MMA passes) ----------------
__global__ __launch_bounds__(256)
void bigmm(const float* __restrict__ X, const float* __restrict__ W, float* __restrict__ Ppart)
{
    __shared__ __nv_bfloat16 AsH[2][128 * ASTRIDE];
    __shared__ __nv_bfloat16 AsL[2][128 * ASTRIDE];
    __shared__ __nv_bfloat16 BsH[2][16 * BSTRIDE];
    __shared__ __nv_bfloat16 BsL[2][16 * BSTRIDE];

    const int t = threadIdx.x;
    const int m0 = blockIdx.y * 128, n0 = blockIdx.x * 128, z = blockIdx.z;
    const int s0 = z * STEPS_PER;
    const int ns = min(STEPS_PER, KSTEPS - s0);

    // global load mapping
    const int am = t >> 1, ak = (t & 1) * 8;       // A: 128 rows x 16 k
    const int bk = t >> 4, bn = (t & 15) * 8;      // B: 16 k x 128 n
    const float* gA = X + (size_t)(m0 + am) * TT + (size_t)s0 * 16 + ak;
    const float* gB = W + (size_t)((size_t)s0 * 16 + bk) * HH + n0 + bn;

    float fa[8], fb[8];

    // warp/frag mapping
    const int lane = t & 31, wid = t >> 5;
    const int wm = wid & 3, wn = wid >> 2;         // 4 m-warps x 2 n-warps

    const unsigned sAH = (unsigned)__cvta_generic_to_shared(&AsH[0][0]);
    const unsigned sAL = (unsigned)__cvta_generic_to_shared(&AsL[0][0]);
    const unsigned sBH = (unsigned)__cvta_generic_to_shared(&BsH[0][0]);
    const unsigned sBL = (unsigned)__cvta_generic_to_shared(&BsL[0][0]);

    // A ldmatrix element offsets (per 16x16 tile)
    unsigned offA[2];
    {
        int arow = lane & 15, acol = (lane >> 4) * 8;
        #pragma unroll
        for (int mt = 0; mt < 2; mt++)
            offA[mt] = (unsigned)(((wm * 32 + mt * 16 + arow) * ASTRIDE + acol) * 2);
    }
    // B ldmatrix.trans offsets (per 16k x 16n region)
    unsigned offB[4];
    {
        int brow = (lane & 7) + ((lane & 16) ? 8 : 0);
        int bcol = (lane & 8) ? 8 : 0;
        #pragma unroll
        for (int p = 0; p < 4; p++)
            offB[p] = (unsigned)((brow * BSTRIDE + wn * 64 + p * 16 + bcol) * 2);
    }

    float acc[2][8][4];
    #pragma unroll
    for (int i = 0; i < 2; i++)
        #pragma unroll
        for (int j = 0; j < 8; j++)
            #pragma unroll
            for (int q = 0; q < 4; q++) acc[i][j][q] = 0.f;

    // prologue: load + convert + store step 0
    {
        float4 v0 = *(const float4*)gA;         float4 v1 = *(const float4*)(gA + 4);
        fa[0]=v0.x; fa[1]=v0.y; fa[2]=v0.z; fa[3]=v0.w; fa[4]=v1.x; fa[5]=v1.y; fa[6]=v1.z; fa[7]=v1.w;
        float4 w0 = *(const float4*)gB;         float4 w1 = *(const float4*)(gB + 4);
        fb[0]=w0.x; fb[1]=w0.y; fb[2]=w0.z; fb[3]=w0.w; fb[4]=w1.x; fb[5]=w1.y; fb[6]=w1.z; fb[7]=w1.w;
    }
    {
        union { __nv_bfloat16 b[8]; uint4 u; } ph, pl;
        #pragma unroll
        for (int j = 0; j < 8; j++) {
            __nv_bfloat16 h = __float2bfloat16(fa[j]);
            ph.b[j] = h; pl.b[j] = __float2bfloat16(fa[j] - __bfloat162float(h));
        }
        *(uint4*)&AsH[0][am * ASTRIDE + ak] = ph.u;
        *(uint4*)&AsL[0][am * ASTRIDE + ak] = pl.u;
        #pragma unroll
        for (int j = 0; j < 8; j++) {
            __nv_bfloat16 h = __float2bfloat16(fb[j]);
            ph.b[j] = h; pl.b[j] = __float2bfloat16(fb[j] - __bfloat162float(h));
        }
        *(uint4*)&BsH[0][bk * BSTRIDE + bn] = ph.u;
        *(uint4*)&BsL[0][bk * BSTRIDE + bn] = pl.u;
    }
    __syncthreads();

    for (int s = 0; s < ns; s++) {
        const int buf = s & 1;

        if (s + 1 < ns) {  // prefetch next step into regs
            const float* pa = gA + (size_t)(s + 1) * 16;
            float4 v0 = *(const float4*)pa;  float4 v1 = *(const float4*)(pa + 4);
            fa[0]=v0.x; fa[1]=v0.y; fa[2]=v0.z; fa[3]=v0.w; fa[4]=v1.x; fa[5]=v1.y; fa[6]=v1.z; fa[7]=v1.w;
            const float* pb = gB + (size_t)(s + 1) * 16 * HH;
            float4 w0 = *(const float4*)pb;  float4 w1 = *(const float4*)(pb + 4);
            fb[0]=w0.x; fb[1]=w0.y; fb[2]=w0.z; fb[3]=w0.w; fb[4]=w1.x; fb[5]=w1.y; fb[6]=w1.z; fb[7]=w1.w;
        }

        // ---- compute from buf ----
        {
            const unsigned aOff = (unsigned)(buf * 128 * ASTRIDE * 2);
            const unsigned bOff = (unsigned)(buf * 16 * BSTRIDE * 2);
            unsigned aH[2][4], aL[2][4];
            ldsm4(aH[0], sAH + aOff + offA[0]);
            ldsm4(aH[1], sAH + aOff + offA[1]);
            ldsm4(aL[0], sAL + aOff + offA[0]);
            ldsm4(aL[1], sAL + aOff + offA[1]);
            unsigned bH[8][2], bL[8][2];
            #pragma unroll
            for (int p = 0; p < 4; p++) {
                unsigned r[4];
                ldsm4t(r, sBH + bOff + offB[p]);
                bH[2*p][0] = r[0]; bH[2*p][1] = r[2]; bH[2*p+1][0] = r[1]; bH[2*p+1][1] = r[3];
                ldsm4t(r, sBL + bOff + offB[p]);
                bL[2*p][0] = r[0]; bL[2*p][1] = r[2]; bL[2*p+1][0] = r[1]; bL[2*p+1][1] = r[3];
            }
            #pragma unroll
            for (int mi = 0; mi < 2; mi++)
                #pragma unroll
                for (int ni = 0; ni < 8; ni++) {
                    mma_bf16(acc[mi][ni], aH[mi], bH[ni]);
                    mma_bf16(acc[mi][ni], aH[mi], bL[ni]);
                    mma_bf16(acc[mi][ni], aL[mi], bH[ni]);
                }
        }

        if (s + 1 < ns) {  // convert + store next step to other buffer
            const int nb = buf ^ 1;
            union { __nv_bfloat16 b[8]; uint4 u; } ph, pl;
            #pragma unroll
            for (int j = 0; j < 8; j++) {
                __nv_bfloat16 h = __float2bfloat16(fa[j]);
                ph.b[j] = h; pl.b[j] = __float2bfloat16(fa[j] - __bfloat162float(h));
            }
            *(uint4*)&AsH[nb][am * ASTRIDE + ak] = ph.u;
            *(uint4*)&AsL[nb][am * ASTRIDE + ak] = pl.u;
            #pragma unroll
            for (int j = 0; j < 8; j++) {
                __nv_bfloat16 h = __float2bfloat16(fb[j]);
                ph.b[j] = h; pl.b[j] = __float2bfloat16(fb[j] - __bfloat162float(h));
            }
            *(uint4*)&BsH[nb][bk * BSTRIDE + bn] = ph.u;
            *(uint4*)&BsL[nb][bk * BSTRIDE + bn] = pl.u;
        }
        __syncthreads();
    }

    // epilogue: store split-K partial
    float* Po = Ppart + (size_t)z * NN * HH;
    #pragma unroll
    for (int mi = 0; mi < 2; mi++) {
        int row = m0 + wm * 32 + mi * 16 + (lane >> 2);
        #pragma unroll
        for (int ni = 0; ni < 8; ni++) {
            int col = n0 + wn * 64 + ni * 8 + (lane & 3) * 2;
            *(float2*)&Po[(size_t)row * HH + col]       = make_float2(acc[mi][ni][0], acc[mi][ni][1]);
            *(float2*)&Po[(size_t)(row + 8) * HH + col] = make_float2(acc[mi][ni][2], acc[mi][ni][3]);
        }
    }
}

__global__ void k_reduceP() {
    int i = blockIdx.x * blockDim.x + threadIdx.x;   // NN*HH/4 threads
    if (i < NN * HH / 4) {
        float4 s = make_float4(0.f, 0.f, 0.f, 0.f);
        #pragma unroll
        for (int z = 0; z < SPLITK; z++) {
            float4 v = ((const float4*)g_Ppart)[(size_t)z * (NN * HH / 4) + i];
            s.x += v.x; s.y += v.y; s.z += v.z; s.w += v.w;
        }
        ((float4*)g_P)[i] = s;
    }
}

// ---------------- small SIMT GEMM (unchanged, known correct) ----------------
// EPI: 0 = plain store, 1 = bias + relu, 2 = bias only
template <int EPI>
__global__ __launch_bounds__(256)
void gemm_k(const float* __restrict__ A, const float* __restrict__ Bm,
            const float* __restrict__ bias, float* __restrict__ C,
            int M, int N, int K)
{
    __shared__ float As[16 * 64];
    __shared__ float Bs[16 * 64];

    int tid = threadIdx.x;
    int m0 = blockIdx.y * 64, n0 = blockIdx.x * 64;

    int arow = tid >> 2;
    int aq   = (tid & 3) << 2;
    int brow = tid >> 4;
    int bcol = (tid & 15) << 2;

    const float* Aptr = A + (size_t)(m0 + arow) * K + aq;
    const float* Bptr = Bm + (size_t)brow * N + n0 + bcol;

    int ty = tid >> 4, tx = tid & 15;
    float acc[4][4] = {};

    for (int k = 0; k < K; k += 16) {
        float4 av = *(const float4*)(Aptr + k);
        As[(aq + 0) * 64 + arow] = av.x;
        As[(aq + 1) * 64 + arow] = av.y;
        As[(aq + 2) * 64 + arow] = av.z;
        As[(aq + 3) * 64 + arow] = av.w;
        float4 bv = *(const float4*)(Bptr + (size_t)k * N);
        *(float4*)&Bs[brow * 64 + bcol] = bv;
        __syncthreads();

        #pragma unroll
        for (int kk = 0; kk < 16; kk++) {
            float4 a = *(const float4*)&As[kk * 64 + ty * 4];
            float4 b = *(const float4*)&Bs[kk * 64 + tx * 4];
            float ar[4] = {a.x, a.y, a.z, a.w};
            float br[4] = {b.x, b.y, b.z, b.w};
            #pragma unroll
            for (int i = 0; i < 4; i++)
                #pragma unroll
                for (int j = 0; j < 4; j++)
                    acc[i][j] += ar[i] * br[j];
        }
        __syncthreads();
    }

    #pragma unroll
    for (int i = 0; i < 4; i++) {
        int m = m0 + ty * 4 + i;
        int n = n0 + tx * 4;
        float4 v = make_float4(acc[i][0], acc[i][1], acc[i][2], acc[i][3]);
        if (EPI == 1) {
            v.x += bias[n + 0]; v.y += bias[n + 1]; v.z += bias[n + 2]; v.w += bias[n + 3];
            v.x = fmaxf(v.x, 0.f); v.y = fmaxf(v.y, 0.f); v.z = fmaxf(v.z, 0.f); v.w = fmaxf(v.w, 0.f);
        } else if (EPI == 2) {
            v.x += bias[n + 0]; v.y += bias[n + 1]; v.z += bias[n + 2]; v.w += bias[n + 3];
        }
        *(float4*)&C[(size_t)m * N + n] = v;
    }
}

// ---------------- N=1 tail: scorer conv2 + sigmoid ----------------
__global__ void k_q4(const float* __restrict__ Wc2a) {
    int warp = (blockIdx.x * blockDim.x + threadIdx.x) >> 5;
    int lane = threadIdx.x & 31;
    if (warp < NN) {
        float s = 0.f;
        for (int i = lane; i < HH; i += 32) s += g_s[warp * HH + i] * Wc2a[i];
        #pragma unroll
        for (int o = 16; o; o >>= 1) s += __shfl_down_sync(0xFFFFFFFFu, s, o);
        if (lane == 0) g_Q4[warp] = s;
    }
}

__global__ void k_region(const float* __restrict__ bc2a, const float* __restrict__ Wc2b,
                         const float* __restrict__ bc2b, float* __restrict__ out) {
    int warp = (blockIdx.x * blockDim.x + threadIdx.x) >> 5;
    int lane = threadIdx.x & 31;
    if (warp < NN) {
        float s = 0.f;
        for (int i = lane; i < NN; i += 32) s += g_B[warp * NN + i] * g_Q4[i];
        #pragma unroll
        for (int o = 16; o; o >>= 1) s += __shfl_down_sync(0xFFFFFFFFu, s, o);
        if (lane == 0) {
            float u = fmaxf(s + bc2a[0], 0.f);
            float sc = u * Wc2b[0] + bc2b[0];
            out[1 + warp] = 1.f / (1.f + expf(-sc));
        }
    }
}

// ---------------- dementia head ----------------
__global__ void k_dementia(const float* __restrict__ Wd, const float* __restrict__ bd,
                           float* __restrict__ out) {
    __shared__ float red[32];
    int tid = threadIdx.x;
    float s = 0.f;
    for (int i = tid; i < NN * LL; i += 1024) s += g_feat[i] * Wd[i];
    #pragma unroll
    for (int o = 16; o; o >>= 1) s += __shfl_down_sync(0xFFFFFFFFu, s, o);
    if ((tid & 31) == 0) red[tid >> 5] = s;
    __syncthreads();
    if (tid < 32) {
        float v = red[tid];
        #pragma unroll
        for (int o = 16; o; o >>= 1) v += __shfl_down_sync(0xFFFFFFFFu, v, o);
        if (tid == 0) out[0] = 1.f / (1.f + expf(-(v + bd[0])));
    }
}

// ---------------- launch ----------------
extern "C" void kernel_launch(void* const* d_in, const int* in_sizes, int n_in,
                              void* d_out, int out_size) {
    const float* X    = (const float*)d_in[0];
    const int*   idx  = (const int*)d_in[1];
    const float* Ws1a = (const float*)d_in[3];
    const float* bs1a = (const float*)d_in[4];
    const float* Ws1b = (const float*)d_in[5];
    const float* bs1b = (const float*)d_in[6];
    const float* Ws2a = (const float*)d_in[7];
    const float* bs2a = (const float*)d_in[8];
    const float* Ws2b = (const float*)d_in[9];
    const float* bs2b = (const float*)d_in[10];
    const float* Wc1a = (const float*)d_in[11];
    const float* bc1a = (const float*)d_in[12];
    const float* Wc1b = (const float*)d_in[13];
    const float* bc1b = (const float*)d_in[14];
    const float* Wc2a = (const float*)d_in[15];
    const float* bc2a = (const float*)d_in[16];
    const float* Wc2b = (const float*)d_in[17];
    const float* bc2b = (const float*)d_in[18];
    const float* Wd   = (const float*)d_in[19];
    const float* bd   = (const float*)d_in[20];
    float* out = (float*)d_out;

    float *pB, *pPpart, *pP, *pU1, *ph, *pQ2, *pU2, *pfeat, *pQ3, *pU3, *ps;
    cudaGetSymbolAddress((void**)&pB, g_B);
    cudaGetSymbolAddress((void**)&pPpart, g_Ppart);
    cudaGetSymbolAddress((void**)&pP, g_P);
    cudaGetSymbolAddress((void**)&pU1, g_U1);
    cudaGetSymbolAddress((void**)&ph, g_h);
    cudaGetSymbolAddress((void**)&pQ2, g_Q2);
    cudaGetSymbolAddress((void**)&pU2, g_U2);
    cudaGetSymbolAddress((void**)&pfeat, g_feat);
    cudaGetSymbolAddress((void**)&pQ3, g_Q3);
    cudaGetSymbolAddress((void**)&pU3, g_U3);
    cudaGetSymbolAddress((void**)&ps, g_s);

    // Build B = I + A
    k_initB<<<256, 256>>>();
    k_edges<<<(EE + 255) / 256, 256>>>(idx);

    // Big GEMM on tensor cores (bf16-split, split-K): P = X @ Ws1a
    bigmm<<<dim3(4, 2, SPLITK), 256>>>(X, Ws1a, pPpart);
    k_reduceP<<<(NN * HH / 4 + 255) / 256, 256>>>();

    // struct_featurizer conv1
    gemm_k<1><<<dim3(8, 4, 1), 256>>>(pB, pP, bs1a, pU1, NN, HH, NN);
    gemm_k<1><<<dim3(8, 4, 1), 256>>>(pU1, Ws1b, bs1b, ph, NN, HH, HH);

    // conv2
    gemm_k<0><<<dim3(4, 4, 1), 256>>>(ph, Ws2a, nullptr, pQ2, NN, LL, HH);
    gemm_k<1><<<dim3(4, 4, 1), 256>>>(pB, pQ2, bs2a, pU2, NN, LL, NN);
    gemm_k<2><<<dim3(4, 4, 1), 256>>>(pU2, Ws2b, bs2b, pfeat, NN, LL, LL);

    // scorer conv1
    gemm_k<0><<<dim3(8, 4, 1), 256>>>(pfeat, Wc1a, nullptr, pQ3, NN, HH, LL);
    gemm_k<1><<<dim3(8, 4, 1), 256>>>(pB, pQ3, bc1a, pU3, NN, HH, NN);
    gemm_k<1><<<dim3(8, 4, 1), 256>>>(pU3, Wc1b, bc1b, ps, NN, HH, HH);

    // scorer conv2 (N=1) + sigmoid
    k_q4<<<32, 256>>>(Wc2a);
    k_region<<<32, 256>>>(bc2a, Wc2b, bc2b, out);

    // dementia head
    k_dementia<<<1, 1024>>>(Wd, bd, out);
}

// round 3
// speedup vs baseline: 2.6529x; 1.2067x over previous
#include <cuda_runtime.h>
#include <cuda_bf16.h>
#include <math.h>

#define NN 256
#define TT 30000
#define HH 512
#define LL 256
#define EE 32768

#define KSTEPS 1875       // 30000/16
#define SPLITK 18
#define STEPS_PER 105

// bigmm smem stage layout (bytes)
#define ASTRIDE 24        // elems per A row (48B, conflict-free ldmatrix)
#define BSTRIDE 136       // elems per B row (272B)
#define ST_AH 0
#define ST_AL 6144        // 128*24*2
#define ST_BH 12288
#define ST_BL 16640       // +16*136*2
#define STAGE 20992
#define NSTAGE 4
#define SMEM_DYN (STAGE * NSTAGE)   // 83968

// small gemm strides
#define SASTR 24          // 48B
#define SBSTR 72          // 144B

// ---------------- device scratch ----------------
__device__ float g_B[NN * NN];
__device__ __nv_bfloat16 g_Xh[NN * TT], g_Xl[NN * TT];
__device__ __nv_bfloat16 g_Wh[TT * HH], g_Wl[TT * HH];
__device__ float g_Ppart[SPLITK * NN * HH];
__device__ float g_P[NN * HH];
__device__ float g_U1[NN * HH];
__device__ float g_h[NN * HH];
__device__ float g_Q2[NN * LL];
__device__ float g_U2[NN * LL];
__device__ float g_feat[NN * LL];
__device__ float g_Q3[NN * HH];
__device__ float g_U3[NN * HH];
__device__ float g_s[NN * HH];
__device__ float g_Q4[NN];

// ---------------- adjacency ----------------
__global__ void k_initB() {
    int i = blockIdx.x * blockDim.x + threadIdx.x;
    g_B[i] = ((i >> 8) == (i & 255)) ? 1.0f : 0.0f;
}
__global__ void k_edges(const int* __restrict__ idx) {
    int e = blockIdx.x * blockDim.x + threadIdx.x;
    if (e < EE) atomicAdd(&g_B[idx[EE + e] * NN + idx[e]], 1.0f);
}

// ---------------- fp32 -> bf16 hi/lo split ----------------
__global__ void k_cvt(const float* __restrict__ src, __nv_bfloat16* __restrict__ hi,
                      __nv_bfloat16* __restrict__ lo, int n8) {
    int i = blockIdx.x * blockDim.x + threadIdx.x;
    if (i < n8) {
        float4 v0 = ((const float4*)src)[2 * i], v1 = ((const float4*)src)[2 * i + 1];
        float f[8] = {v0.x, v0.y, v0.z, v0.w, v1.x, v1.y, v1.z, v1.w};
        union { __nv_bfloat16 b[8]; uint4 u; } H, L;
        #pragma unroll
        for (int j = 0; j < 8; j++) {
            __nv_bfloat16 h = __float2bfloat16(f[j]);
            H.b[j] = h; L.b[j] = __float2bfloat16(f[j] - __bfloat162float(h));
        }
        ((uint4*)hi)[i] = H.u;
        ((uint4*)lo)[i] = L.u;
    }
}

// ---------------- PTX helpers ----------------
__device__ __forceinline__ void mma_bf16(float* c, const unsigned* a, const unsigned* b) {
    asm volatile(
        "mma.sync.aligned.m16n8k16.row.col.f32.bf16.bf16.f32 "
        "{%0,%1,%2,%3},{%4,%5,%6,%7},{%8,%9},{%0,%1,%2,%3};"
        : "+f"(c[0]), "+f"(c[1]), "+f"(c[2]), "+f"(c[3])
        : "r"(a[0]), "r"(a[1]), "r"(a[2]), "r"(a[3]), "r"(b[0]), "r"(b[1]));
}
__device__ __forceinline__ void ldsm4(unsigned* r, unsigned addr) {
    asm volatile("ldmatrix.sync.aligned.m8n8.x4.shared.b16 {%0,%1,%2,%3},[%4];"
                 : "=r"(r[0]), "=r"(r[1]), "=r"(r[2]), "=r"(r[3]) : "r"(addr));
}
__device__ __forceinline__ void ldsm4t(unsigned* r, unsigned addr) {
    asm volatile("ldmatrix.sync.aligned.m8n8.x4.trans.shared.b16 {%0,%1,%2,%3},[%4];"
                 : "=r"(r[0]), "=r"(r[1]), "=r"(r[2]), "=r"(r[3]) : "r"(addr));
}
__device__ __forceinline__ void cpa16(unsigned dst, const void* src) {
    asm volatile("cp.async.cg.shared.global [%0], [%1], 16;" :: "r"(dst), "l"(src));
}
__device__ __forceinline__ void cpa_commit() { asm volatile("cp.async.commit_group;"); }
template <int N> __device__ __forceinline__ void cpa_wait() {
    asm volatile("cp.async.wait_group %0;" :: "n"(N));
}

// ---------------- big GEMM: cp.async pipelined, bf16 3-pass ----------------
__global__ __launch_bounds__(256, 1)
void bigmm2(float* __restrict__ Ppart)
{
    extern __shared__ char dyn[];
    const unsigned sb = (unsigned)__cvta_generic_to_shared(dyn);

    const int t = threadIdx.x;
    const int m0 = blockIdx.y * 128, n0 = blockIdx.x * 128, z = blockIdx.z;
    const int s0 = z * STEPS_PER;
    const int ns = min(STEPS_PER, KSTEPS - s0);

    // copy mapping
    const int arow = t >> 1, ach = t & 1;     // 128 rows x 2 chunks(16B)
    const int brow = t >> 4, bch = t & 15;    // 16 rows x 16 chunks
    const __nv_bfloat16* gAh = g_Xh + (size_t)(m0 + arow) * TT + (size_t)s0 * 16 + ach * 8;
    const __nv_bfloat16* gAl = g_Xl + (size_t)(m0 + arow) * TT + (size_t)s0 * 16 + ach * 8;
    const __nv_bfloat16* gBh = g_Wh + (size_t)((size_t)s0 * 16 + brow) * HH + n0 + bch * 8;
    const __nv_bfloat16* gBl = g_Wl + (size_t)((size_t)s0 * 16 + brow) * HH + n0 + bch * 8;
    const unsigned dA = arow * 48 + ach * 16;
    const unsigned dB = brow * 272 + bch * 16;

    // frag mapping
    const int lane = t & 31, wid = t >> 5;
    const int wm = wid & 3, wn = wid >> 2;
    unsigned offA[2], offB[4];
    {
        int r = lane & 15, c = (lane >> 4) * 8;
        offA[0] = ((wm * 32 + r) * ASTRIDE + c) * 2;
        offA[1] = ((wm * 32 + 16 + r) * ASTRIDE + c) * 2;
        int br = (lane & 7) + ((lane & 16) ? 8 : 0);
        int bc = (lane & 8) ? 8 : 0;
        #pragma unroll
        for (int p = 0; p < 4; p++)
            offB[p] = (br * BSTRIDE + wn * 64 + p * 16 + bc) * 2;
    }

    float acc[2][8][4];
    #pragma unroll
    for (int i = 0; i < 2; i++)
        #pragma unroll
        for (int j = 0; j < 8; j++)
            #pragma unroll
            for (int q = 0; q < 4; q++) acc[i][j][q] = 0.f;

    // prologue: issue NSTAGE-1 stages
    #pragma unroll
    for (int sg = 0; sg < NSTAGE - 1; sg++) {
        unsigned base = sb + sg * STAGE;
        cpa16(base + ST_AH + dA, gAh + sg * 16);
        cpa16(base + ST_AL + dA, gAl + sg * 16);
        cpa16(base + ST_BH + dB, gBh + (size_t)sg * 16 * HH);
        cpa16(base + ST_BL + dB, gBl + (size_t)sg * 16 * HH);
        cpa_commit();
    }

    for (int s = 0; s < ns; s++) {
        cpa_wait<NSTAGE - 2>();
        __syncthreads();

        int sg = s + NSTAGE - 1;
        if (sg < ns) {
            unsigned base = sb + (sg & (NSTAGE - 1)) * STAGE;
            cpa16(base + ST_AH + dA, gAh + (size_t)sg * 16);
            cpa16(base + ST_AL + dA, gAl + (size_t)sg * 16);
            cpa16(base + ST_BH + dB, gBh + (size_t)sg * 16 * HH);
            cpa16(base + ST_BL + dB, gBl + (size_t)sg * 16 * HH);
        }
        cpa_commit();   // commit every iter to keep group accounting uniform

        unsigned base = sb + (s & (NSTAGE - 1)) * STAGE;
        unsigned aH[2][4], aL[2][4];
        ldsm4(aH[0], base + ST_AH + offA[0]);
        ldsm4(aH[1], base + ST_AH + offA[1]);
        ldsm4(aL[0], base + ST_AL + offA[0]);
        ldsm4(aL[1], base + ST_AL + offA[1]);
        unsigned bH[8][2], bL[8][2];
        #pragma unroll
        for (int p = 0; p < 4; p++) {
            unsigned r[4];
            ldsm4t(r, base + ST_BH + offB[p]);
            bH[2*p][0] = r[0]; bH[2*p][1] = r[2]; bH[2*p+1][0] = r[1]; bH[2*p+1][1] = r[3];
            ldsm4t(r, base + ST_BL + offB[p]);
            bL[2*p][0] = r[0]; bL[2*p][1] = r[2]; bL[2*p+1][0] = r[1]; bL[2*p+1][1] = r[3];
        }
        #pragma unroll
        for (int mi = 0; mi < 2; mi++)
            #pragma unroll
            for (int ni = 0; ni < 8; ni++) {
                mma_bf16(acc[mi][ni], aH[mi], bH[ni]);
                mma_bf16(acc[mi][ni], aH[mi], bL[ni]);
                mma_bf16(acc[mi][ni], aL[mi], bH[ni]);
            }
        __syncthreads();
    }

    float* Po = Ppart + (size_t)z * NN * HH;
    #pragma unroll
    for (int mi = 0; mi < 2; mi++) {
        int row = m0 + wm * 32 + mi * 16 + (lane >> 2);
        #pragma unroll
        for (int ni = 0; ni < 8; ni++) {
            int col = n0 + wn * 64 + ni * 8 + (lane & 3) * 2;
            *(float2*)&Po[(size_t)row * HH + col]       = make_float2(acc[mi][ni][0], acc[mi][ni][1]);
            *(float2*)&Po[(size_t)(row + 8) * HH + col] = make_float2(acc[mi][ni][2], acc[mi][ni][3]);
        }
    }
}

__global__ void k_reduceP() {
    int i = blockIdx.x * blockDim.x + threadIdx.x;
    if (i < NN * HH / 4) {
        float4 s = make_float4(0.f, 0.f, 0.f, 0.f);
        #pragma unroll
        for (int z = 0; z < SPLITK; z++) {
            float4 v = ((const float4*)g_Ppart)[(size_t)z * (NN * HH / 4) + i];
            s.x += v.x; s.y += v.y; s.z += v.z; s.w += v.w;
        }
        ((float4*)g_P)[i] = s;
    }
}

// ---------------- small MMA GEMM: C = epi(A@B + bias), 64x64 tiles ----------------
// EPI: 0 plain, 1 bias+relu, 2 bias
template <int EPI>
__global__ __launch_bounds__(128)
void gemm_t(const float* __restrict__ A, const float* __restrict__ Bm,
            const float* __restrict__ bias, float* __restrict__ C,
            int M, int N, int K)
{
    __shared__ __nv_bfloat16 AsH[2][64 * SASTR], AsL[2][64 * SASTR];
    __shared__ __nv_bfloat16 BsH[2][16 * SBSTR], BsL[2][16 * SBSTR];

    const int t = threadIdx.x;
    const int m0 = blockIdx.y * 64, n0 = blockIdx.x * 64;
    const int ns = K >> 4;

    const int arow = t >> 1, ak = (t & 1) * 8;
    const int brow = t >> 3, bn = (t & 7) * 8;
    const float* gA = A + (size_t)(m0 + arow) * K + ak;
    const float* gB = Bm + (size_t)brow * N + n0 + bn;

    const int lane = t & 31, wid = t >> 5;
    const int wm = wid & 1, wn = wid >> 1;

    const unsigned sAH = (unsigned)__cvta_generic_to_shared(&AsH[0][0]);
    const unsigned sAL = (unsigned)__cvta_generic_to_shared(&AsL[0][0]);
    const unsigned sBH = (unsigned)__cvta_generic_to_shared(&BsH[0][0]);
    const unsigned sBL = (unsigned)__cvta_generic_to_shared(&BsL[0][0]);

    unsigned offA[2], offB[2];
    {
        int r = lane & 15, c = (lane >> 4) * 8;
        offA[0] = ((wm * 32 + r) * SASTR + c) * 2;
        offA[1] = ((wm * 32 + 16 + r) * SASTR + c) * 2;
        int br = (lane & 7) + ((lane & 16) ? 8 : 0);
        int bc = (lane & 8) ? 8 : 0;
        offB[0] = (br * SBSTR + wn * 32 + bc) * 2;
        offB[1] = (br * SBSTR + wn * 32 + 16 + bc) * 2;
    }

    float fa[8], fb[8];
    float acc[2][4][4];
    #pragma unroll
    for (int i = 0; i < 2; i++)
        #pragma unroll
        for (int j = 0; j < 4; j++)
            #pragma unroll
            for (int q = 0; q < 4; q++) acc[i][j][q] = 0.f;

    // prologue
    {
        float4 v0 = *(const float4*)gA, v1 = *(const float4*)(gA + 4);
        fa[0]=v0.x; fa[1]=v0.y; fa[2]=v0.z; fa[3]=v0.w; fa[4]=v1.x; fa[5]=v1.y; fa[6]=v1.z; fa[7]=v1.w;
        float4 w0 = *(const float4*)gB, w1 = *(const float4*)(gB + 4);
        fb[0]=w0.x; fb[1]=w0.y; fb[2]=w0.z; fb[3]=w0.w; fb[4]=w1.x; fb[5]=w1.y; fb[6]=w1.z; fb[7]=w1.w;
        union { __nv_bfloat16 b[8]; uint4 u; } ph, pl;
        #pragma unroll
        for (int j = 0; j < 8; j++) {
            __nv_bfloat16 h = __float2bfloat16(fa[j]);
            ph.b[j] = h; pl.b[j] = __float2bfloat16(fa[j] - __bfloat162float(h));
        }
        *(uint4*)&AsH[0][arow * SASTR + ak] = ph.u;
        *(uint4*)&AsL[0][arow * SASTR + ak] = pl.u;
        #pragma unroll
        for (int j = 0; j < 8; j++) {
            __nv_bfloat16 h = __float2bfloat16(fb[j]);
            ph.b[j] = h; pl.b[j] = __float2bfloat16(fb[j] - __bfloat162float(h));
        }
        *(uint4*)&BsH[0][brow * SBSTR + bn] = ph.u;
        *(uint4*)&BsL[0][brow * SBSTR + bn] = pl.u;
    }
    __syncthreads();

    for (int s = 0; s < ns; s++) {
        const int buf = s & 1;
        if (s + 1 < ns) {
            const float* pa = gA + (size_t)(s + 1) * 16;
            float4 v0 = *(const float4*)pa, v1 = *(const float4*)(pa + 4);
            fa[0]=v0.x; fa[1]=v0.y; fa[2]=v0.z; fa[3]=v0.w; fa[4]=v1.x; fa[5]=v1.y; fa[6]=v1.z; fa[7]=v1.w;
            const float* pb = gB + (size_t)(s + 1) * 16 * N;
            float4 w0 = *(const float4*)pb, w1 = *(const float4*)(pb + 4);
            fb[0]=w0.x; fb[1]=w0.y; fb[2]=w0.z; fb[3]=w0.w; fb[4]=w1.x; fb[5]=w1.y; fb[6]=w1.z; fb[7]=w1.w;
        }

        {
            const unsigned aOff = (unsigned)(buf * 64 * SASTR * 2);
            const unsigned bOff = (unsigned)(buf * 16 * SBSTR * 2);
            unsigned aH[2][4], aL[2][4];
            ldsm4(aH[0], sAH + aOff + offA[0]);
            ldsm4(aH[1], sAH + aOff + offA[1]);
            ldsm4(aL[0], sAL + aOff + offA[0]);
            ldsm4(aL[1], sAL + aOff + offA[1]);
            unsigned bH[4][2], bL[4][2];
            #pragma unroll
            for (int p = 0; p < 2; p++) {
                unsigned r[4];
                ldsm4t(r, sBH + bOff + offB[p]);
                bH[2*p][0] = r[0]; bH[2*p][1] = r[2]; bH[2*p+1][0] = r[1]; bH[2*p+1][1] = r[3];
                ldsm4t(r, sBL + bOff + offB[p]);
                bL[2*p][0] = r[0]; bL[2*p][1] = r[2]; bL[2*p+1][0] = r[1]; bL[2*p+1][1] = r[3];
            }
            #pragma unroll
            for (int mi = 0; mi < 2; mi++)
                #pragma unroll
                for (int ni = 0; ni < 4; ni++) {
                    mma_bf16(acc[mi][ni], aH[mi], bH[ni]);
                    mma_bf16(acc[mi][ni], aH[mi], bL[ni]);
                    mma_bf16(acc[mi][ni], aL[mi], bH[ni]);
                }
        }

        if (s + 1 < ns) {
            const int nb = buf ^ 1;
            union { __nv_bfloat16 b[8]; uint4 u; } ph, pl;
            #pragma unroll
            for (int j = 0; j < 8; j++) {
                __nv_bfloat16 h = __float2bfloat16(fa[j]);
                ph.b[j] = h; pl.b[j] = __float2bfloat16(fa[j] - __bfloat162float(h));
            }
            *(uint4*)&AsH[nb][arow * SASTR + ak] = ph.u;
            *(uint4*)&AsL[nb][arow * SASTR + ak] = pl.u;
            #pragma unroll
            for (int j = 0; j < 8; j++) {
                __nv_bfloat16 h = __float2bfloat16(fb[j]);
                ph.b[j] = h; pl.b[j] = __float2bfloat16(fb[j] - __bfloat162float(h));
            }
            *(uint4*)&BsH[nb][brow * SBSTR + bn] = ph.u;
            *(uint4*)&BsL[nb][brow * SBSTR + bn] = pl.u;
        }
        __syncthreads();
    }

    #pragma unroll
    for (int mi = 0; mi < 2; mi++) {
        int row = m0 + wm * 32 + mi * 16 + (lane >> 2);
        #pragma unroll
        for (int ni = 0; ni < 4; ni++) {
            int col = n0 + wn * 32 + ni * 8 + (lane & 3) * 2;
            float2 v0 = make_float2(acc[mi][ni][0], acc[mi][ni][1]);
            float2 v1 = make_float2(acc[mi][ni][2], acc[mi][ni][3]);
            if (EPI == 1 || EPI == 2) {
                float2 b = *(const float2*)&bias[col];
                v0.x += b.x; v0.y += b.y; v1.x += b.x; v1.y += b.y;
            }
            if (EPI == 1) {
                v0.x = fmaxf(v0.x, 0.f); v0.y = fmaxf(v0.y, 0.f);
                v1.x = fmaxf(v1.x, 0.f); v1.y = fmaxf(v1.y, 0.f);
            }
            *(float2*)&C[(size_t)row * N + col]       = v0;
            *(float2*)&C[(size_t)(row + 8) * N + col] = v1;
        }
    }
}

// ---------------- tails ----------------
__global__ void k_q4(const float* __restrict__ Wc2a) {
    int warp = (blockIdx.x * blockDim.x + threadIdx.x) >> 5;
    int lane = threadIdx.x & 31;
    if (warp < NN) {
        float s = 0.f;
        for (int i = lane; i < HH; i += 32) s += g_s[warp * HH + i] * Wc2a[i];
        #pragma unroll
        for (int o = 16; o; o >>= 1) s += __shfl_down_sync(0xFFFFFFFFu, s, o);
        if (lane == 0) g_Q4[warp] = s;
    }
}

__global__ void k_region(const float* __restrict__ bc2a, const float* __restrict__ Wc2b,
                         const float* __restrict__ bc2b, float* __restrict__ out) {
    int warp = (blockIdx.x * blockDim.x + threadIdx.x) >> 5;
    int lane = threadIdx.x & 31;
    if (warp < NN) {
        float s = 0.f;
        for (int i = lane; i < NN; i += 32) s += g_B[warp * NN + i] * g_Q4[i];
        #pragma unroll
        for (int o = 16; o; o >>= 1) s += __shfl_down_sync(0xFFFFFFFFu, s, o);
        if (lane == 0) {
            float u = fmaxf(s + bc2a[0], 0.f);
            float sc = u * Wc2b[0] + bc2b[0];
            out[1 + warp] = 1.f / (1.f + expf(-sc));
        }
    }
}

__global__ void k_dementia(const float* __restrict__ Wd, const float* __restrict__ bd,
                           float* __restrict__ out) {
    __shared__ float red[32];
    int tid = threadIdx.x;
    float s = 0.f;
    for (int i = tid; i < NN * LL; i += 1024) s += g_feat[i] * Wd[i];
    #pragma unroll
    for (int o = 16; o; o >>= 1) s += __shfl_down_sync(0xFFFFFFFFu, s, o);
    if ((tid & 31) == 0) red[tid >> 5] = s;
    __syncthreads();
    if (tid < 32) {
        float v = red[tid];
        #pragma unroll
        for (int o = 16; o; o >>= 1) v += __shfl_down_sync(0xFFFFFFFFu, v, o);
        if (tid == 0) out[0] = 1.f / (1.f + expf(-(v + bd[0])));
    }
}

// ---------------- launch ----------------
extern "C" void kernel_launch(void* const* d_in, const int* in_sizes, int n_in,
                              void* d_out, int out_size) {
    const float* X    = (const float*)d_in[0];
    const int*   idx  = (const int*)d_in[1];
    const float* Ws1a = (const float*)d_in[3];
    const float* bs1a = (const float*)d_in[4];
    const float* Ws1b = (const float*)d_in[5];
    const float* bs1b = (const float*)d_in[6];
    const float* Ws2a = (const float*)d_in[7];
    const float* bs2a = (const float*)d_in[8];
    const float* Ws2b = (const float*)d_in[9];
    const float* bs2b = (const float*)d_in[10];
    const float* Wc1a = (const float*)d_in[11];
    const float* bc1a = (const float*)d_in[12];
    const float* Wc1b = (const float*)d_in[13];
    const float* bc1b = (const float*)d_in[14];
    const float* Wc2a = (const float*)d_in[15];
    const float* bc2a = (const float*)d_in[16];
    const float* Wc2b = (const float*)d_in[17];
    const float* bc2b = (const float*)d_in[18];
    const float* Wd   = (const float*)d_in[19];
    const float* bd   = (const float*)d_in[20];
    float* out = (float*)d_out;

    float *pB, *pPpart, *pP, *pU1, *ph, *pQ2, *pU2, *pfeat, *pQ3, *pU3, *ps;
    __nv_bfloat16 *pXh, *pXl, *pWh, *pWl;
    cudaGetSymbolAddress((void**)&pB, g_B);
    cudaGetSymbolAddress((void**)&pPpart, g_Ppart);
    cudaGetSymbolAddress((void**)&pP, g_P);
    cudaGetSymbolAddress((void**)&pU1, g_U1);
    cudaGetSymbolAddress((void**)&ph, g_h);
    cudaGetSymbolAddress((void**)&pQ2, g_Q2);
    cudaGetSymbolAddress((void**)&pU2, g_U2);
    cudaGetSymbolAddress((void**)&pfeat, g_feat);
    cudaGetSymbolAddress((void**)&pQ3, g_Q3);
    cudaGetSymbolAddress((void**)&pU3, g_U3);
    cudaGetSymbolAddress((void**)&ps, g_s);
    cudaGetSymbolAddress((void**)&pXh, g_Xh);
    cudaGetSymbolAddress((void**)&pXl, g_Xl);
    cudaGetSymbolAddress((void**)&pWh, g_Wh);
    cudaGetSymbolAddress((void**)&pWl, g_Wl);

    static int smem_set = 0;
    if (!smem_set) {
        cudaFuncSetAttribute(bigmm2, cudaFuncAttributeMaxDynamicSharedMemorySize, SMEM_DYN);
        smem_set = 1;
    }

    // adjacency + conversions
    k_initB<<<256, 256>>>();
    k_edges<<<(EE + 255) / 256, 256>>>(idx);
    k_cvt<<<(NN * TT / 8 + 255) / 256, 256>>>(X, pXh, pXl, NN * TT / 8);
    k_cvt<<<(TT * HH / 8 + 255) / 256, 256>>>(Ws1a, pWh, pWl, TT * HH / 8);

    // big GEMM: P = X @ Ws1a
    bigmm2<<<dim3(4, 2, SPLITK), 256, SMEM_DYN>>>(pPpart);
    k_reduceP<<<(NN * HH / 4 + 255) / 256, 256>>>();

    // struct_featurizer
    gemm_t<1><<<dim3(8, 4), 128>>>(pB, pP, bs1a, pU1, NN, HH, NN);
    gemm_t<1><<<dim3(8, 4), 128>>>(pU1, Ws1b, bs1b, ph, NN, HH, HH);
    gemm_t<0><<<dim3(4, 4), 128>>>(ph, Ws2a, nullptr, pQ2, NN, LL, HH);
    gemm_t<1><<<dim3(4, 4), 128>>>(pB, pQ2, bs2a, pU2, NN, LL, NN);
    gemm_t<2><<<dim3(4, 4), 128>>>(pU2, Ws2b, bs2b, pfeat, NN, LL, LL);

    // gin_scorer
    gemm_t<0><<<dim3(8, 4), 128>>>(pfeat, Wc1a, nullptr, pQ3, NN, HH, LL);
    gemm_t<1><<<dim3(8, 4), 128>>>(pB, pQ3, bc1a, pU3, NN, HH, NN);
    gemm_t<1><<<dim3(8, 4), 128>>>(pU3, Wc1b, bc1b, ps, NN, HH, HH);

    // tails
    k_q4<<<32, 256>>>(Wc2a);
    k_region<<<32, 256>>>(bc2a, Wc2b, bc2b, out);
    k_dementia<<<1, 1024>>>(Wd, bd, out);
}

// round 5
// speedup vs baseline: 2.6995x; 1.0176x over previous
#include <cuda_runtime.h>
#include <cuda_bf16.h>
#include <math.h>

#define NN 256
#define TT 30000
#define HH 512
#define LL 256
#define EE 32768

#define KSTEPS 1875        // 30000/16
#define SPLITKZ 37
#define SPG 51             // k16-steps per z (last z: 39)

// bigmm smem stage layout (bytes)
#define ASTRIDE 24         // bf16 elems per A smem row (48B, conflict-free ldmatrix)
#define BSTRIDE 136        // bf16 elems per B smem row (272B, conflict-free ldmatrix.trans)
#define ST_AH 0
#define ST_AL 6144         // 128*24*2
#define ST_BH 12288
#define ST_BL 16640        // +16*136*2
#define STAGE 20992
#define NSTAGE 4
#define SMEM_DYN (STAGE * NSTAGE)   // 83968 -> 2 CTAs/SM = 168KB

// small gemm strides
#define SASTR 24
#define SBSTR 72

// ---------------- device scratch ----------------
__device__ float g_B[NN * NN];
__device__ __nv_bfloat16 g_Xh[NN * TT], g_Xl[NN * TT];
__device__ __nv_bfloat16 g_Wh[TT * HH], g_Wl[TT * HH];
__device__ float g_Ppart[SPLITKZ * NN * HH];
__device__ float g_P[NN * HH];
__device__ float g_U1[NN * HH];
__device__ float g_h[NN * HH];
__device__ float g_Q2[NN * LL];
__device__ float g_U2[NN * LL];
__device__ float g_feat[NN * LL];
__device__ float g_Q3[NN * HH];
__device__ float g_U3[NN * HH];
__device__ float g_s[NN * HH];
__device__ float g_Q4[NN];

// ---------------- adjacency ----------------
__global__ void k_initB() {
    int i = blockIdx.x * blockDim.x + threadIdx.x;
    g_B[i] = ((i >> 8) == (i & 255)) ? 1.0f : 0.0f;
}
__global__ void k_edges(const int* __restrict__ idx) {
    int e = blockIdx.x * blockDim.x + threadIdx.x;
    if (e < EE) atomicAdd(&g_B[idx[EE + e] * NN + idx[e]], 1.0f);
}

// ---------------- fp32 -> bf16 hi/lo split ----------------
__global__ void k_cvt(const float* __restrict__ src, __nv_bfloat16* __restrict__ hi,
                      __nv_bfloat16* __restrict__ lo, int n8) {
    int i = blockIdx.x * blockDim.x + threadIdx.x;
    if (i < n8) {
        float4 v0 = ((const float4*)src)[2 * i], v1 = ((const float4*)src)[2 * i + 1];
        float f[8] = {v0.x, v0.y, v0.z, v0.w, v1.x, v1.y, v1.z, v1.w};
        union { __nv_bfloat16 b[8]; uint4 u; } H, L;
        #pragma unroll
        for (int j = 0; j < 8; j++) {
            __nv_bfloat16 h = __float2bfloat16(f[j]);
            H.b[j] = h; L.b[j] = __float2bfloat16(f[j] - __bfloat162float(h));
        }
        ((uint4*)hi)[i] = H.u;
        ((uint4*)lo)[i] = L.u;
    }
}

// ---------------- PTX helpers ----------------
__device__ __forceinline__ void mma_bf16(float* c, const unsigned* a, const unsigned* b) {
    asm volatile(
        "mma.sync.aligned.m16n8k16.row.col.f32.bf16.bf16.f32 "
        "{%0,%1,%2,%3},{%4,%5,%6,%7},{%8,%9},{%0,%1,%2,%3};"
        : "+f"(c[0]), "+f"(c[1]), "+f"(c[2]), "+f"(c[3])
        : "r"(a[0]), "r"(a[1]), "r"(a[2]), "r"(a[3]), "r"(b[0]), "r"(b[1]));
}
__device__ __forceinline__ void ldsm4(unsigned* r, unsigned addr) {
    asm volatile("ldmatrix.sync.aligned.m8n8.x4.shared.b16 {%0,%1,%2,%3},[%4];"
                 : "=r"(r[0]), "=r"(r[1]), "=r"(r[2]), "=r"(r[3]) : "r"(addr));
}
__device__ __forceinline__ void ldsm4t(unsigned* r, unsigned addr) {
    asm volatile("ldmatrix.sync.aligned.m8n8.x4.trans.shared.b16 {%0,%1,%2,%3},[%4];"
                 : "=r"(r[0]), "=r"(r[1]), "=r"(r[2]), "=r"(r[3]) : "r"(addr));
}
__device__ __forceinline__ void cpa16(unsigned dst, const void* src) {
    asm volatile("cp.async.cg.shared.global [%0], [%1], 16;" :: "r"(dst), "l"(src));
}
__device__ __forceinline__ void cpa_commit() { asm volatile("cp.async.commit_group;"); }
template <int N> __device__ __forceinline__ void cpa_wait() {
    asm volatile("cp.async.wait_group %0;" :: "n"(N));
}

// ---------------- big GEMM: mma.sync, cp.async 4-stage, 2 CTAs/SM ----------------
__global__ __launch_bounds__(256, 2)
void bigmm3(float* __restrict__ Ppart)
{
    extern __shared__ char dyn[];
    const unsigned sb = (unsigned)__cvta_generic_to_shared(dyn);

    const int t = threadIdx.x;
    const int m0 = blockIdx.y * 128, n0 = blockIdx.x * 128, z = blockIdx.z;
    const int s0 = z * SPG;
    const int ns = min(SPG, KSTEPS - s0);

    // cp.async mapping
    const int arow = t >> 1, ach = t & 1;     // A: 128 rows x 2 16B-chunks
    const int brow = t >> 4, bch = t & 15;    // B: 16 rows x 16 chunks
    const __nv_bfloat16* gAh = g_Xh + (size_t)(m0 + arow) * TT + (size_t)s0 * 16 + ach * 8;
    const __nv_bfloat16* gAl = g_Xl + (size_t)(m0 + arow) * TT + (size_t)s0 * 16 + ach * 8;
    const __nv_bfloat16* gBh = g_Wh + (size_t)((size_t)s0 * 16 + brow) * HH + n0 + bch * 8;
    const __nv_bfloat16* gBl = g_Wl + (size_t)((size_t)s0 * 16 + brow) * HH + n0 + bch * 8;
    const unsigned dA = arow * 48 + ach * 16;
    const unsigned dB = brow * 272 + bch * 16;

    // fragment mapping
    const int lane = t & 31, wid = t >> 5;
    const int wm = wid & 3, wn = wid >> 2;    // 4 m-warps x 2 n-warps (32x64 each)
    unsigned offA[2], offB[4];
    {
        int r = lane & 15, c = (lane >> 4) * 8;
        offA[0] = ((wm * 32 + r) * ASTRIDE + c) * 2;
        offA[1] = ((wm * 32 + 16 + r) * ASTRIDE + c) * 2;
        int br = (lane & 7) + ((lane & 16) ? 8 : 0);
        int bc = (lane & 8) ? 8 : 0;
        #pragma unroll
        for (int p = 0; p < 4; p++)
            offB[p] = (br * BSTRIDE + wn * 64 + p * 16 + bc) * 2;
    }

    float acc[2][8][4];
    #pragma unroll
    for (int i = 0; i < 2; i++)
        #pragma unroll
        for (int j = 0; j < 8; j++)
            #pragma unroll
            for (int q = 0; q < 4; q++) acc[i][j][q] = 0.f;

    // prologue: stages 0..2
    #pragma unroll
    for (int sg = 0; sg < NSTAGE - 1; sg++) {
        if (sg < ns) {
            unsigned base = sb + sg * STAGE;
            cpa16(base + ST_AH + dA, gAh + sg * 16);
            cpa16(base + ST_AL + dA, gAl + sg * 16);
            cpa16(base + ST_BH + dB, gBh + (size_t)sg * 16 * HH);
            cpa16(base + ST_BL + dB, gBl + (size_t)sg * 16 * HH);
        }
        cpa_commit();
    }

    for (int s = 0; s < ns; s++) {
        cpa_wait<NSTAGE - 2>();
        __syncthreads();

        int sg = s + NSTAGE - 1;
        if (sg < ns) {
            unsigned base = sb + (sg & (NSTAGE - 1)) * STAGE;
            cpa16(base + ST_AH + dA, gAh + (size_t)sg * 16);
            cpa16(base + ST_AL + dA, gAl + (size_t)sg * 16);
            cpa16(base + ST_BH + dB, gBh + (size_t)sg * 16 * HH);
            cpa16(base + ST_BL + dB, gBl + (size_t)sg * 16 * HH);
        }
        cpa_commit();

        const unsigned base = sb + (s & (NSTAGE - 1)) * STAGE;
        unsigned aH[2][4], aL[2][4];
        ldsm4(aH[0], base + ST_AH + offA[0]);
        ldsm4(aH[1], base + ST_AH + offA[1]);
        ldsm4(aL[0], base + ST_AL + offA[0]);
        ldsm4(aL[1], base + ST_AL + offA[1]);
        #pragma unroll
        for (int p = 0; p < 4; p++) {
            unsigned r[4], q[4];
            ldsm4t(r, base + ST_BH + offB[p]);
            ldsm4t(q, base + ST_BL + offB[p]);
            unsigned bh0[2] = {r[0], r[2]}, bh1[2] = {r[1], r[3]};
            unsigned bl0[2] = {q[0], q[2]}, bl1[2] = {q[1], q[3]};
            #pragma unroll
            for (int mi = 0; mi < 2; mi++) {
                mma_bf16(acc[mi][2 * p],     aH[mi], bh0);
                mma_bf16(acc[mi][2 * p],     aH[mi], bl0);
                mma_bf16(acc[mi][2 * p],     aL[mi], bh0);
                mma_bf16(acc[mi][2 * p + 1], aH[mi], bh1);
                mma_bf16(acc[mi][2 * p + 1], aH[mi], bl1);
                mma_bf16(acc[mi][2 * p + 1], aL[mi], bh1);
            }
        }
    }

    // epilogue: split-K partial
    float* Po = Ppart + (size_t)z * NN * HH;
    #pragma unroll
    for (int mi = 0; mi < 2; mi++) {
        int row = m0 + wm * 32 + mi * 16 + (lane >> 2);
        #pragma unroll
        for (int ni = 0; ni < 8; ni++) {
            int col = n0 + wn * 64 + ni * 8 + (lane & 3) * 2;
            *(float2*)&Po[(size_t)row * HH + col]       = make_float2(acc[mi][ni][0], acc[mi][ni][1]);
            *(float2*)&Po[(size_t)(row + 8) * HH + col] = make_float2(acc[mi][ni][2], acc[mi][ni][3]);
        }
    }
}

__global__ void k_reduceP() {
    int i = blockIdx.x * blockDim.x + threadIdx.x;
    if (i < NN * HH / 4) {
        float4 s = make_float4(0.f, 0.f, 0.f, 0.f);
        #pragma unroll
        for (int z = 0; z < SPLITKZ; z++) {
            float4 v = ((const float4*)g_Ppart)[(size_t)z * (NN * HH / 4) + i];
            s.x += v.x; s.y += v.y; s.z += v.z; s.w += v.w;
        }
        ((float4*)g_P)[i] = s;
    }
}

// ---------------- small MMA GEMM chain (known correct) ----------------
template <int EPI>
__global__ __launch_bounds__(128)
void gemm_t(const float* __restrict__ A, const float* __restrict__ Bm,
            const float* __restrict__ bias, float* __restrict__ C,
            int M, int N, int K)
{
    __shared__ __nv_bfloat16 AsH[2][64 * SASTR], AsL[2][64 * SASTR];
    __shared__ __nv_bfloat16 BsH[2][16 * SBSTR], BsL[2][16 * SBSTR];

    const int t = threadIdx.x;
    const int m0 = blockIdx.y * 64, n0 = blockIdx.x * 64;
    const int ns = K >> 4;

    const int arow = t >> 1, ak = (t & 1) * 8;
    const int brow = t >> 3, bn = (t & 7) * 8;
    const float* gA = A + (size_t)(m0 + arow) * K + ak;
    const float* gB = Bm + (size_t)brow * N + n0 + bn;

    const int lane = t & 31, wid = t >> 5;
    const int wm = wid & 1, wn = wid >> 1;

    const unsigned sAH = (unsigned)__cvta_generic_to_shared(&AsH[0][0]);
    const unsigned sAL = (unsigned)__cvta_generic_to_shared(&AsL[0][0]);
    const unsigned sBH = (unsigned)__cvta_generic_to_shared(&BsH[0][0]);
    const unsigned sBL = (unsigned)__cvta_generic_to_shared(&BsL[0][0]);

    unsigned offA[2], offB[2];
    {
        int r = lane & 15, c = (lane >> 4) * 8;
        offA[0] = ((wm * 32 + r) * SASTR + c) * 2;
        offA[1] = ((wm * 32 + 16 + r) * SASTR + c) * 2;
        int br = (lane & 7) + ((lane & 16) ? 8 : 0);
        int bc = (lane & 8) ? 8 : 0;
        offB[0] = (br * SBSTR + wn * 32 + bc) * 2;
        offB[1] = (br * SBSTR + wn * 32 + 16 + bc) * 2;
    }

    float fa[8], fb[8];
    float acc[2][4][4];
    #pragma unroll
    for (int i = 0; i < 2; i++)
        #pragma unroll
        for (int j = 0; j < 4; j++)
            #pragma unroll
            for (int q = 0; q < 4; q++) acc[i][j][q] = 0.f;

    {
        float4 v0 = *(const float4*)gA, v1 = *(const float4*)(gA + 4);
        fa[0]=v0.x; fa[1]=v0.y; fa[2]=v0.z; fa[3]=v0.w; fa[4]=v1.x; fa[5]=v1.y; fa[6]=v1.z; fa[7]=v1.w;
        float4 w0 = *(const float4*)gB, w1 = *(const float4*)(gB + 4);
        fb[0]=w0.x; fb[1]=w0.y; fb[2]=w0.z; fb[3]=w0.w; fb[4]=w1.x; fb[5]=w1.y; fb[6]=w1.z; fb[7]=w1.w;
        union { __nv_bfloat16 b[8]; uint4 u; } ph, pl;
        #pragma unroll
        for (int j = 0; j < 8; j++) {
            __nv_bfloat16 h = __float2bfloat16(fa[j]);
            ph.b[j] = h; pl.b[j] = __float2bfloat16(fa[j] - __bfloat162float(h));
        }
        *(uint4*)&AsH[0][arow * SASTR + ak] = ph.u;
        *(uint4*)&AsL[0][arow * SASTR + ak] = pl.u;
        #pragma unroll
        for (int j = 0; j < 8; j++) {
            __nv_bfloat16 h = __float2bfloat16(fb[j]);
            ph.b[j] = h; pl.b[j] = __float2bfloat16(fb[j] - __bfloat162float(h));
        }
        *(uint4*)&BsH[0][brow * SBSTR + bn] = ph.u;
        *(uint4*)&BsL[0][brow * SBSTR + bn] = pl.u;
    }
    __syncthreads();

    for (int s = 0; s < ns; s++) {
        const int buf = s & 1;
        if (s + 1 < ns) {
            const float* pa = gA + (size_t)(s + 1) * 16;
            float4 v0 = *(const float4*)pa, v1 = *(const float4*)(pa + 4);
            fa[0]=v0.x; fa[1]=v0.y; fa[2]=v0.z; fa[3]=v0.w; fa[4]=v1.x; fa[5]=v1.y; fa[6]=v1.z; fa[7]=v1.w;
            const float* pb = gB + (size_t)(s + 1) * 16 * N;
            float4 w0 = *(const float4*)pb, w1 = *(const float4*)(pb + 4);
            fb[0]=w0.x; fb[1]=w0.y; fb[2]=w0.z; fb[3]=w0.w; fb[4]=w1.x; fb[5]=w1.y; fb[6]=w1.z; fb[7]=w1.w;
        }

        {
            const unsigned aOff = (unsigned)(buf * 64 * SASTR * 2);
            const unsigned bOff = (unsigned)(buf * 16 * SBSTR * 2);
            unsigned aH[2][4], aL[2][4];
            ldsm4(aH[0], sAH + aOff + offA[0]);
            ldsm4(aH[1], sAH + aOff + offA[1]);
            ldsm4(aL[0], sAL + aOff + offA[0]);
            ldsm4(aL[1], sAL + aOff + offA[1]);
            unsigned bH[4][2], bL[4][2];
            #pragma unroll
            for (int p = 0; p < 2; p++) {
                unsigned r[4];
                ldsm4t(r, sBH + bOff + offB[p]);
                bH[2*p][0] = r[0]; bH[2*p][1] = r[2]; bH[2*p+1][0] = r[1]; bH[2*p+1][1] = r[3];
                ldsm4t(r, sBL + bOff + offB[p]);
                bL[2*p][0] = r[0]; bL[2*p][1] = r[2]; bL[2*p+1][0] = r[1]; bL[2*p+1][1] = r[3];
            }
            #pragma unroll
            for (int mi = 0; mi < 2; mi++)
                #pragma unroll
                for (int ni = 0; ni < 4; ni++) {
                    mma_bf16(acc[mi][ni], aH[mi], bH[ni]);
                    mma_bf16(acc[mi][ni], aH[mi], bL[ni]);
                    mma_bf16(acc[mi][ni], aL[mi], bH[ni]);
                }
        }

        if (s + 1 < ns) {
            const int nb = buf ^ 1;
            union { __nv_bfloat16 b[8]; uint4 u; } ph, pl;
            #pragma unroll
            for (int j = 0; j < 8; j++) {
                __nv_bfloat16 h = __float2bfloat16(fa[j]);
                ph.b[j] = h; pl.b[j] = __float2bfloat16(fa[j] - __bfloat162float(h));
            }
            *(uint4*)&AsH[nb][arow * SASTR + ak] = ph.u;
            *(uint4*)&AsL[nb][arow * SASTR + ak] = pl.u;
            #pragma unroll
            for (int j = 0; j < 8; j++) {
                __nv_bfloat16 h = __float2bfloat16(fb[j]);
                ph.b[j] = h; pl.b[j] = __float2bfloat16(fb[j] - __bfloat162float(h));
            }
            *(uint4*)&BsH[nb][brow * SBSTR + bn] = ph.u;
            *(uint4*)&BsL[nb][brow * SBSTR + bn] = pl.u;
        }
        __syncthreads();
    }

    #pragma unroll
    for (int mi = 0; mi < 2; mi++) {
        int row = m0 + wm * 32 + mi * 16 + (lane >> 2);
        #pragma unroll
        for (int ni = 0; ni < 4; ni++) {
            int col = n0 + wn * 32 + ni * 8 + (lane & 3) * 2;
            float2 v0 = make_float2(acc[mi][ni][0], acc[mi][ni][1]);
            float2 v1 = make_float2(acc[mi][ni][2], acc[mi][ni][3]);
            if (EPI == 1 || EPI == 2) {
                float2 b = *(const float2*)&bias[col];
                v0.x += b.x; v0.y += b.y; v1.x += b.x; v1.y += b.y;
            }
            if (EPI == 1) {
                v0.x = fmaxf(v0.x, 0.f); v0.y = fmaxf(v0.y, 0.f);
                v1.x = fmaxf(v1.x, 0.f); v1.y = fmaxf(v1.y, 0.f);
            }
            *(float2*)&C[(size_t)row * N + col]       = v0;
            *(float2*)&C[(size_t)(row + 8) * N + col] = v1;
        }
    }
}

// ---------------- tails ----------------
__global__ void k_q4(const float* __restrict__ Wc2a) {
    int warp = (blockIdx.x * blockDim.x + threadIdx.x) >> 5;
    int lane = threadIdx.x & 31;
    if (warp < NN) {
        float s = 0.f;
        for (int i = lane; i < HH; i += 32) s += g_s[warp * HH + i] * Wc2a[i];
        #pragma unroll
        for (int o = 16; o; o >>= 1) s += __shfl_down_sync(0xFFFFFFFFu, s, o);
        if (lane == 0) g_Q4[warp] = s;
    }
}

__global__ void k_region(const float* __restrict__ bc2a, const float* __restrict__ Wc2b,
                         const float* __restrict__ bc2b, float* __restrict__ out) {
    int warp = (blockIdx.x * blockDim.x + threadIdx.x) >> 5;
    int lane = threadIdx.x & 31;
    if (warp < NN) {
        float s = 0.f;
        for (int i = lane; i < NN; i += 32) s += g_B[warp * NN + i] * g_Q4[i];
        #pragma unroll
        for (int o = 16; o; o >>= 1) s += __shfl_down_sync(0xFFFFFFFFu, s, o);
        if (lane == 0) {
            float u = fmaxf(s + bc2a[0], 0.f);
            float sc = u * Wc2b[0] + bc2b[0];
            out[1 + warp] = 1.f / (1.f + expf(-sc));
        }
    }
}

__global__ void k_dementia(const float* __restrict__ Wd, const float* __restrict__ bd,
                           float* __restrict__ out) {
    __shared__ float red[32];
    int tid = threadIdx.x;
    float s = 0.f;
    for (int i = tid; i < NN * LL; i += 1024) s += g_feat[i] * Wd[i];
    #pragma unroll
    for (int o = 16; o; o >>= 1) s += __shfl_down_sync(0xFFFFFFFFu, s, o);
    if ((tid & 31) == 0) red[tid >> 5] = s;
    __syncthreads();
    if (tid < 32) {
        float v = red[tid];
        #pragma unroll
        for (int o = 16; o; o >>= 1) v += __shfl_down_sync(0xFFFFFFFFu, v, o);
        if (tid == 0) out[0] = 1.f / (1.f + expf(-(v + bd[0])));
    }
}

// ---------------- launch ----------------
extern "C" void kernel_launch(void* const* d_in, const int* in_sizes, int n_in,
                              void* d_out, int out_size) {
    const float* X    = (const float*)d_in[0];
    const int*   idx  = (const int*)d_in[1];
    const float* Ws1a = (const float*)d_in[3];
    const float* bs1a = (const float*)d_in[4];
    const float* Ws1b = (const float*)d_in[5];
    const float* bs1b = (const float*)d_in[6];
    const float* Ws2a = (const float*)d_in[7];
    const float* bs2a = (const float*)d_in[8];
    const float* Ws2b = (const float*)d_in[9];
    const float* bs2b = (const float*)d_in[10];
    const float* Wc1a = (const float*)d_in[11];
    const float* bc1a = (const float*)d_in[12];
    const float* Wc1b = (const float*)d_in[13];
    const float* bc1b = (const float*)d_in[14];
    const float* Wc2a = (const float*)d_in[15];
    const float* bc2a = (const float*)d_in[16];
    const float* Wc2b = (const float*)d_in[17];
    const float* bc2b = (const float*)d_in[18];
    const float* Wd   = (const float*)d_in[19];
    const float* bd   = (const float*)d_in[20];
    float* out = (float*)d_out;

    float *pB, *pPpart, *pP, *pU1, *ph, *pQ2, *pU2, *pfeat, *pQ3, *pU3, *ps;
    __nv_bfloat16 *pXh, *pXl, *pWh, *pWl;
    cudaGetSymbolAddress((void**)&pB, g_B);
    cudaGetSymbolAddress((void**)&pPpart, g_Ppart);
    cudaGetSymbolAddress((void**)&pP, g_P);
    cudaGetSymbolAddress((void**)&pU1, g_U1);
    cudaGetSymbolAddress((void**)&ph, g_h);
    cudaGetSymbolAddress((void**)&pQ2, g_Q2);
    cudaGetSymbolAddress((void**)&pU2, g_U2);
    cudaGetSymbolAddress((void**)&pfeat, g_feat);
    cudaGetSymbolAddress((void**)&pQ3, g_Q3);
    cudaGetSymbolAddress((void**)&pU3, g_U3);
    cudaGetSymbolAddress((void**)&ps, g_s);
    cudaGetSymbolAddress((void**)&pXh, g_Xh);
    cudaGetSymbolAddress((void**)&pXl, g_Xl);
    cudaGetSymbolAddress((void**)&pWh, g_Wh);
    cudaGetSymbolAddress((void**)&pWl, g_Wl);

    cudaFuncSetAttribute(bigmm3, cudaFuncAttributeMaxDynamicSharedMemorySize, SMEM_DYN);

    // launches ordered so bigmm3 is #4 (the slot ncu captures)
    k_cvt<<<(NN * TT / 8 + 255) / 256, 256>>>(X, pXh, pXl, NN * TT / 8);        // 1
    k_cvt<<<(TT * HH / 8 + 255) / 256, 256>>>(Ws1a, pWh, pWl, TT * HH / 8);     // 2
    k_initB<<<256, 256>>>();                                                     // 3
    bigmm3<<<dim3(4, 2, SPLITKZ), 256, SMEM_DYN>>>(pPpart);                      // 4
    k_edges<<<(EE + 255) / 256, 256>>>(idx);                                     // 5
    k_reduceP<<<(NN * HH / 4 + 255) / 256, 256>>>();                             // 6

    // struct_featurizer
    gemm_t<1><<<dim3(8, 4), 128>>>(pB, pP, bs1a, pU1, NN, HH, NN);
    gemm_t<1><<<dim3(8, 4), 128>>>(pU1, Ws1b, bs1b, ph, NN, HH, HH);
    gemm_t<0><<<dim3(4, 4), 128>>>(ph, Ws2a, nullptr, pQ2, NN, LL, HH);
    gemm_t<1><<<dim3(4, 4), 128>>>(pB, pQ2, bs2a, pU2, NN, LL, NN);
    gemm_t<2><<<dim3(4, 4), 128>>>(pU2, Ws2b, bs2b, pfeat, NN, LL, LL);

    // gin_scorer
    gemm_t<0><<<dim3(8, 4), 128>>>(pfeat, Wc1a, nullptr, pQ3, NN, HH, LL);
    gemm_t<1><<<dim3(8, 4), 128>>>(pB, pQ3, bc1a, pU3, NN, HH, NN);
    gemm_t<1><<<dim3(8, 4), 128>>>(pU3, Wc1b, bc1b, ps, NN, HH, HH);

    // tails
    k_q4<<<32, 256>>>(Wc2a);
    k_region<<<32, 256>>>(bc2a, Wc2b, bc2b, out);
    k_dementia<<<1, 1024>>>(Wd, bd, out);
}

// round 6
// speedup vs baseline: 2.9740x; 1.1017x over previous
#include <cuda_runtime.h>
#include <cuda_bf16.h>
#include <math.h>

#define NN 256
#define TT 30000
#define HH 512
#define LL 256
#define EE 32768

#define KSTEPS 1875        // 30000/16
#define SPLITKZ 37
#define SPG 51             // k16-steps per z (last z: 39)

// bigmm smem stage layout (bytes)
#define ASTRIDE 24
#define BSTRIDE 136
#define ST_AH 0
#define ST_AL 6144
#define ST_BH 12288
#define ST_BL 16640
#define STAGE 20992
#define NSTAGE 4
#define SMEM_DYN (STAGE * NSTAGE)   // 83968 -> 2 CTAs/SM

// small gemm strides
#define SASTR 24
#define SBSTR 72

#define NCTA 32

// ---------------- device scratch ----------------
__device__ float g_B[NN * NN];
__device__ __nv_bfloat16 g_Xh[NN * TT], g_Xl[NN * TT];
__device__ __nv_bfloat16 g_Wh[TT * HH], g_Wl[TT * HH];
__device__ float g_Ppart[SPLITKZ * NN * HH];
__device__ float g_P[NN * HH];
__device__ float g_U1[NN * HH];
__device__ float g_h[NN * HH];
__device__ float g_Q2[NN * LL];
__device__ float g_U2[NN * LL];
__device__ float g_feat[NN * LL];
__device__ float g_Q3[NN * HH];
__device__ float g_U3[NN * HH];
__device__ float g_s[NN * HH];
__device__ float g_Q4[NN];
__device__ float g_dpart[NCTA];
__device__ unsigned g_bar_cnt;
__device__ unsigned g_bar_gen;

// ---------------- fp32 -> bf16 hi/lo split ----------------
__global__ void k_cvt(const float* __restrict__ src, __nv_bfloat16* __restrict__ hi,
                      __nv_bfloat16* __restrict__ lo, int n8) {
    int i = blockIdx.x * blockDim.x + threadIdx.x;
    if (i < n8) {
        float4 v0 = ((const float4*)src)[2 * i], v1 = ((const float4*)src)[2 * i + 1];
        float f[8] = {v0.x, v0.y, v0.z, v0.w, v1.x, v1.y, v1.z, v1.w};
        union { __nv_bfloat16 b[8]; uint4 u; } H, L;
        #pragma unroll
        for (int j = 0; j < 8; j++) {
            __nv_bfloat16 h = __float2bfloat16(f[j]);
            H.b[j] = h; L.b[j] = __float2bfloat16(f[j] - __bfloat162float(h));
        }
        ((uint4*)hi)[i] = H.u;
        ((uint4*)lo)[i] = L.u;
    }
}

// ---------------- PTX helpers ----------------
__device__ __forceinline__ void mma_bf16(float* c, const unsigned* a, const unsigned* b) {
    asm volatile(
        "mma.sync.aligned.m16n8k16.row.col.f32.bf16.bf16.f32 "
        "{%0,%1,%2,%3},{%4,%5,%6,%7},{%8,%9},{%0,%1,%2,%3};"
        : "+f"(c[0]), "+f"(c[1]), "+f"(c[2]), "+f"(c[3])
        : "r"(a[0]), "r"(a[1]), "r"(a[2]), "r"(a[3]), "r"(b[0]), "r"(b[1]));
}
__device__ __forceinline__ void ldsm4(unsigned* r, unsigned addr) {
    asm volatile("ldmatrix.sync.aligned.m8n8.x4.shared.b16 {%0,%1,%2,%3},[%4];"
                 : "=r"(r[0]), "=r"(r[1]), "=r"(r[2]), "=r"(r[3]) : "r"(addr));
}
__device__ __forceinline__ void ldsm4t(unsigned* r, unsigned addr) {
    asm volatile("ldmatrix.sync.aligned.m8n8.x4.trans.shared.b16 {%0,%1,%2,%3},[%4];"
                 : "=r"(r[0]), "=r"(r[1]), "=r"(r[2]), "=r"(r[3]) : "r"(addr));
}
__device__ __forceinline__ void cpa16(unsigned dst, const void* src) {
    asm volatile("cp.async.cg.shared.global [%0], [%1], 16;" :: "r"(dst), "l"(src));
}
__device__ __forceinline__ void cpa_commit() { asm volatile("cp.async.commit_group;"); }
template <int N> __device__ __forceinline__ void cpa_wait() {
    asm volatile("cp.async.wait_group %0;" :: "n"(N));
}

// ---------------- big GEMM (unchanged from R5 passing kernel) ----------------
__global__ __launch_bounds__(256, 2)
void bigmm3(float* __restrict__ Ppart)
{
    extern __shared__ char dyn[];
    const unsigned sb = (unsigned)__cvta_generic_to_shared(dyn);

    const int t = threadIdx.x;
    const int m0 = blockIdx.y * 128, n0 = blockIdx.x * 128, z = blockIdx.z;
    const int s0 = z * SPG;
    const int ns = min(SPG, KSTEPS - s0);

    const int arow = t >> 1, ach = t & 1;
    const int brow = t >> 4, bch = t & 15;
    const __nv_bfloat16* gAh = g_Xh + (size_t)(m0 + arow) * TT + (size_t)s0 * 16 + ach * 8;
    const __nv_bfloat16* gAl = g_Xl + (size_t)(m0 + arow) * TT + (size_t)s0 * 16 + ach * 8;
    const __nv_bfloat16* gBh = g_Wh + (size_t)((size_t)s0 * 16 + brow) * HH + n0 + bch * 8;
    const __nv_bfloat16* gBl = g_Wl + (size_t)((size_t)s0 * 16 + brow) * HH + n0 + bch * 8;
    const unsigned dA = arow * 48 + ach * 16;
    const unsigned dB = brow * 272 + bch * 16;

    const int lane = t & 31, wid = t >> 5;
    const int wm = wid & 3, wn = wid >> 2;
    unsigned offA[2], offB[4];
    {
        int r = lane & 15, c = (lane >> 4) * 8;
        offA[0] = ((wm * 32 + r) * ASTRIDE + c) * 2;
        offA[1] = ((wm * 32 + 16 + r) * ASTRIDE + c) * 2;
        int br = (lane & 7) + ((lane & 16) ? 8 : 0);
        int bc = (lane & 8) ? 8 : 0;
        #pragma unroll
        for (int p = 0; p < 4; p++)
            offB[p] = (br * BSTRIDE + wn * 64 + p * 16 + bc) * 2;
    }

    float acc[2][8][4];
    #pragma unroll
    for (int i = 0; i < 2; i++)
        #pragma unroll
        for (int j = 0; j < 8; j++)
            #pragma unroll
            for (int q = 0; q < 4; q++) acc[i][j][q] = 0.f;

    #pragma unroll
    for (int sg = 0; sg < NSTAGE - 1; sg++) {
        if (sg < ns) {
            unsigned base = sb + sg * STAGE;
            cpa16(base + ST_AH + dA, gAh + sg * 16);
            cpa16(base + ST_AL + dA, gAl + sg * 16);
            cpa16(base + ST_BH + dB, gBh + (size_t)sg * 16 * HH);
            cpa16(base + ST_BL + dB, gBl + (size_t)sg * 16 * HH);
        }
        cpa_commit();
    }

    for (int s = 0; s < ns; s++) {
        cpa_wait<NSTAGE - 2>();
        __syncthreads();

        int sg = s + NSTAGE - 1;
        if (sg < ns) {
            unsigned base = sb + (sg & (NSTAGE - 1)) * STAGE;
            cpa16(base + ST_AH + dA, gAh + (size_t)sg * 16);
            cpa16(base + ST_AL + dA, gAl + (size_t)sg * 16);
            cpa16(base + ST_BH + dB, gBh + (size_t)sg * 16 * HH);
            cpa16(base + ST_BL + dB, gBl + (size_t)sg * 16 * HH);
        }
        cpa_commit();

        const unsigned base = sb + (s & (NSTAGE - 1)) * STAGE;
        unsigned aH[2][4], aL[2][4];
        ldsm4(aH[0], base + ST_AH + offA[0]);
        ldsm4(aH[1], base + ST_AH + offA[1]);
        ldsm4(aL[0], base + ST_AL + offA[0]);
        ldsm4(aL[1], base + ST_AL + offA[1]);
        #pragma unroll
        for (int p = 0; p < 4; p++) {
            unsigned r[4], q[4];
            ldsm4t(r, base + ST_BH + offB[p]);
            ldsm4t(q, base + ST_BL + offB[p]);
            unsigned bh0[2] = {r[0], r[2]}, bh1[2] = {r[1], r[3]};
            unsigned bl0[2] = {q[0], q[2]}, bl1[2] = {q[1], q[3]};
            #pragma unroll
            for (int mi = 0; mi < 2; mi++) {
                mma_bf16(acc[mi][2 * p],     aH[mi], bh0);
                mma_bf16(acc[mi][2 * p],     aH[mi], bl0);
                mma_bf16(acc[mi][2 * p],     aL[mi], bh0);
                mma_bf16(acc[mi][2 * p + 1], aH[mi], bh1);
                mma_bf16(acc[mi][2 * p + 1], aH[mi], bl1);
                mma_bf16(acc[mi][2 * p + 1], aL[mi], bh1);
            }
        }
    }

    float* Po = Ppart + (size_t)z * NN * HH;
    #pragma unroll
    for (int mi = 0; mi < 2; mi++) {
        int row = m0 + wm * 32 + mi * 16 + (lane >> 2);
        #pragma unroll
        for (int ni = 0; ni < 8; ni++) {
            int col = n0 + wn * 64 + ni * 8 + (lane & 3) * 2;
            *(float2*)&Po[(size_t)row * HH + col]       = make_float2(acc[mi][ni][0], acc[mi][ni][1]);
            *(float2*)&Po[(size_t)(row + 8) * HH + col] = make_float2(acc[mi][ni][2], acc[mi][ni][3]);
        }
    }
}

// ---------------- device-wide barrier (graph-replay safe) ----------------
__device__ __forceinline__ void gbar() {
    __syncthreads();
    if (threadIdx.x == 0) {
        __threadfence();
        unsigned old = *(volatile unsigned*)&g_bar_gen;
        unsigned a = atomicAdd(&g_bar_cnt, 1u);
        if (a == NCTA - 1) {
            g_bar_cnt = 0;
            __threadfence();
            *(volatile unsigned*)&g_bar_gen = old + 1;
        } else {
            while (*(volatile unsigned*)&g_bar_gen == old) __nanosleep(64);
        }
        __threadfence();
    }
    __syncthreads();
}

// ---------------- 64x64 bf16-split MMA tile (device function) ----------------
__device__ void dgemm64(const float* __restrict__ A, const float* __restrict__ Bm,
                        const float* __restrict__ bias, float* __restrict__ C,
                        int N, int K, int m0, int n0, int epi,
                        __nv_bfloat16* AsH, __nv_bfloat16* AsL,
                        __nv_bfloat16* BsH, __nv_bfloat16* BsL)
{
    const int t = threadIdx.x;
    const int ns = K >> 4;

    const int arow = t >> 1, ak = (t & 1) * 8;
    const int brow = t >> 3, bn = (t & 7) * 8;
    const float* gA = A + (size_t)(m0 + arow) * K + ak;
    const float* gB = Bm + (size_t)brow * N + n0 + bn;

    const int lane = t & 31, wid = t >> 5;
    const int wm = wid & 1, wn = wid >> 1;

    const unsigned sAH = (unsigned)__cvta_generic_to_shared(AsH);
    const unsigned sAL = (unsigned)__cvta_generic_to_shared(AsL);
    const unsigned sBH = (unsigned)__cvta_generic_to_shared(BsH);
    const unsigned sBL = (unsigned)__cvta_generic_to_shared(BsL);

    unsigned offA[2], offB[2];
    {
        int r = lane & 15, c = (lane >> 4) * 8;
        offA[0] = ((wm * 32 + r) * SASTR + c) * 2;
        offA[1] = ((wm * 32 + 16 + r) * SASTR + c) * 2;
        int br = (lane & 7) + ((lane & 16) ? 8 : 0);
        int bc = (lane & 8) ? 8 : 0;
        offB[0] = (br * SBSTR + wn * 32 + bc) * 2;
        offB[1] = (br * SBSTR + wn * 32 + 16 + bc) * 2;
    }

    float fa[8], fb[8];
    float acc[2][4][4];
    #pragma unroll
    for (int i = 0; i < 2; i++)
        #pragma unroll
        for (int j = 0; j < 4; j++)
            #pragma unroll
            for (int q = 0; q < 4; q++) acc[i][j][q] = 0.f;

    {
        float4 v0 = *(const float4*)gA, v1 = *(const float4*)(gA + 4);
        fa[0]=v0.x; fa[1]=v0.y; fa[2]=v0.z; fa[3]=v0.w; fa[4]=v1.x; fa[5]=v1.y; fa[6]=v1.z; fa[7]=v1.w;
        float4 w0 = *(const float4*)gB, w1 = *(const float4*)(gB + 4);
        fb[0]=w0.x; fb[1]=w0.y; fb[2]=w0.z; fb[3]=w0.w; fb[4]=w1.x; fb[5]=w1.y; fb[6]=w1.z; fb[7]=w1.w;
        union { __nv_bfloat16 b[8]; uint4 u; } ph, pl;
        #pragma unroll
        for (int j = 0; j < 8; j++) {
            __nv_bfloat16 h = __float2bfloat16(fa[j]);
            ph.b[j] = h; pl.b[j] = __float2bfloat16(fa[j] - __bfloat162float(h));
        }
        *(uint4*)&AsH[arow * SASTR + ak] = ph.u;
        *(uint4*)&AsL[arow * SASTR + ak] = pl.u;
        #pragma unroll
        for (int j = 0; j < 8; j++) {
            __nv_bfloat16 h = __float2bfloat16(fb[j]);
            ph.b[j] = h; pl.b[j] = __float2bfloat16(fb[j] - __bfloat162float(h));
        }
        *(uint4*)&BsH[brow * SBSTR + bn] = ph.u;
        *(uint4*)&BsL[brow * SBSTR + bn] = pl.u;
    }
    __syncthreads();

    for (int s = 0; s < ns; s++) {
        const int buf = s & 1;
        if (s + 1 < ns) {
            const float* pa = gA + (size_t)(s + 1) * 16;
            float4 v0 = *(const float4*)pa, v1 = *(const float4*)(pa + 4);
            fa[0]=v0.x; fa[1]=v0.y; fa[2]=v0.z; fa[3]=v0.w; fa[4]=v1.x; fa[5]=v1.y; fa[6]=v1.z; fa[7]=v1.w;
            const float* pb = gB + (size_t)(s + 1) * 16 * N;
            float4 w0 = *(const float4*)pb, w1 = *(const float4*)(pb + 4);
            fb[0]=w0.x; fb[1]=w0.y; fb[2]=w0.z; fb[3]=w0.w; fb[4]=w1.x; fb[5]=w1.y; fb[6]=w1.z; fb[7]=w1.w;
        }

        {
            const unsigned aOff = (unsigned)(buf * 64 * SASTR * 2);
            const unsigned bOff = (unsigned)(buf * 16 * SBSTR * 2);
            unsigned aH[2][4], aL[2][4];
            ldsm4(aH[0], sAH + aOff + offA[0]);
            ldsm4(aH[1], sAH + aOff + offA[1]);
            ldsm4(aL[0], sAL + aOff + offA[0]);
            ldsm4(aL[1], sAL + aOff + offA[1]);
            unsigned bH[4][2], bL[4][2];
            #pragma unroll
            for (int p = 0; p < 2; p++) {
                unsigned r[4];
                ldsm4t(r, sBH + bOff + offB[p]);
                bH[2*p][0] = r[0]; bH[2*p][1] = r[2]; bH[2*p+1][0] = r[1]; bH[2*p+1][1] = r[3];
                ldsm4t(r, sBL + bOff + offB[p]);
                bL[2*p][0] = r[0]; bL[2*p][1] = r[2]; bL[2*p+1][0] = r[1]; bL[2*p+1][1] = r[3];
            }
            #pragma unroll
            for (int mi = 0; mi < 2; mi++)
                #pragma unroll
                for (int ni = 0; ni < 4; ni++) {
                    mma_bf16(acc[mi][ni], aH[mi], bH[ni]);
                    mma_bf16(acc[mi][ni], aH[mi], bL[ni]);
                    mma_bf16(acc[mi][ni], aL[mi], bH[ni]);
                }
        }

        if (s + 1 < ns) {
            const int nb = buf ^ 1;
            union { __nv_bfloat16 b[8]; uint4 u; } ph, pl;
            #pragma unroll
            for (int j = 0; j < 8; j++) {
                __nv_bfloat16 h = __float2bfloat16(fa[j]);
                ph.b[j] = h; pl.b[j] = __float2bfloat16(fa[j] - __bfloat162float(h));
            }
            *(uint4*)&AsH[nb * 64 * SASTR + arow * SASTR + ak] = ph.u;
            *(uint4*)&AsL[nb * 64 * SASTR + arow * SASTR + ak] = pl.u;
            #pragma unroll
            for (int j = 0; j < 8; j++) {
                __nv_bfloat16 h = __float2bfloat16(fb[j]);
                ph.b[j] = h; pl.b[j] = __float2bfloat16(fb[j] - __bfloat162float(h));
            }
            *(uint4*)&BsH[nb * 16 * SBSTR + brow * SBSTR + bn] = ph.u;
            *(uint4*)&BsL[nb * 16 * SBSTR + brow * SBSTR + bn] = pl.u;
        }
        __syncthreads();
    }

    #pragma unroll
    for (int mi = 0; mi < 2; mi++) {
        int row = m0 + wm * 32 + mi * 16 + (lane >> 2);
        #pragma unroll
        for (int ni = 0; ni < 4; ni++) {
            int col = n0 + wn * 32 + ni * 8 + (lane & 3) * 2;
            float2 v0 = make_float2(acc[mi][ni][0], acc[mi][ni][1]);
            float2 v1 = make_float2(acc[mi][ni][2], acc[mi][ni][3]);
            if (epi) {
                float2 b = *(const float2*)&bias[col];
                v0.x += b.x; v0.y += b.y; v1.x += b.x; v1.y += b.y;
            }
            if (epi == 1) {
                v0.x = fmaxf(v0.x, 0.f); v0.y = fmaxf(v0.y, 0.f);
                v1.x = fmaxf(v1.x, 0.f); v1.y = fmaxf(v1.y, 0.f);
            }
            *(float2*)&C[(size_t)row * N + col]       = v0;
            *(float2*)&C[(size_t)(row + 8) * N + col] = v1;
        }
    }
}

// ---------------- persistent chain kernel ----------------
__global__ __launch_bounds__(128)
void k_chain(const int* __restrict__ idx,
             const float* __restrict__ bs1a, const float* __restrict__ Ws1b, const float* __restrict__ bs1b,
             const float* __restrict__ Ws2a, const float* __restrict__ bs2a,
             const float* __restrict__ Ws2b, const float* __restrict__ bs2b,
             const float* __restrict__ Wc1a, const float* __restrict__ bc1a,
             const float* __restrict__ Wc1b, const float* __restrict__ bc1b,
             const float* __restrict__ Wc2a, const float* __restrict__ bc2a,
             const float* __restrict__ Wc2b, const float* __restrict__ bc2b,
             const float* __restrict__ Wd, const float* __restrict__ bd,
             float* __restrict__ out)
{
    __shared__ __nv_bfloat16 AsH[2 * 64 * SASTR], AsL[2 * 64 * SASTR];
    __shared__ __nv_bfloat16 BsH[2 * 16 * SBSTR], BsL[2 * 16 * SBSTR];
    __shared__ float dred[4];

    const int bid = blockIdx.x, t = threadIdx.x;
    const int gid = bid * 128 + t;              // 0..4095
    const int wid = t >> 5, lane = t & 31;

    // ---- phase 0a: B identity init + reduceP ----
    #pragma unroll
    for (int j = 0; j < 4; j++) {
        int i4 = gid + j * 4096;                // float4 index (16384 total)
        int e0 = i4 * 4;
        float4 v = make_float4(0.f, 0.f, 0.f, 0.f);
        float* pv = &v.x;
        #pragma unroll
        for (int q = 0; q < 4; q++) {
            int e = e0 + q;
            if ((e >> 8) == (e & 255)) pv[q] = 1.f;
        }
        ((float4*)g_B)[i4] = v;
    }
    #pragma unroll
    for (int j = 0; j < 8; j++) {
        int i = gid + j * 4096;                 // float4 index (32768 total)
        float4 s = make_float4(0.f, 0.f, 0.f, 0.f);
        #pragma unroll
        for (int z = 0; z < SPLITKZ; z++) {
            float4 v = ((const float4*)g_Ppart)[(size_t)z * (NN * HH / 4) + i];
            s.x += v.x; s.y += v.y; s.z += v.z; s.w += v.w;
        }
        ((float4*)g_P)[i] = s;
    }
    gbar();

    // ---- phase 0b: edge atomics ----
    #pragma unroll
    for (int j = 0; j < 8; j++) {
        int e = gid + j * 4096;
        atomicAdd(&g_B[idx[EE + e] * NN + idx[e]], 1.0f);
    }
    gbar();

    // tile coords
    const int tx8 = bid & 7, ty8 = bid >> 3;    // 8n x 4m (32 tiles)
    const int tx4 = bid & 3, ty4 = bid >> 2;    // 4n x 4m (16 tiles)

    // G1: U1 = relu(B @ P + bs1a)  [256,512] K=256
    dgemm64(g_B, g_P, bs1a, g_U1, HH, NN, ty8 * 64, tx8 * 64, 1, AsH, AsL, BsH, BsL);
    gbar();
    // G2: h = relu(U1 @ Ws1b + bs1b)  [256,512] K=512
    dgemm64(g_U1, Ws1b, bs1b, g_h, HH, HH, ty8 * 64, tx8 * 64, 1, AsH, AsL, BsH, BsL);
    gbar();
    // G3: Q2 = h @ Ws2a  [256,256] K=512
    if (bid < 16) dgemm64(g_h, Ws2a, (const float*)0, g_Q2, LL, HH, ty4 * 64, tx4 * 64, 0, AsH, AsL, BsH, BsL);
    gbar();
    // G4: U2 = relu(B @ Q2 + bs2a)  [256,256] K=256
    if (bid < 16) dgemm64(g_B, g_Q2, bs2a, g_U2, LL, NN, ty4 * 64, tx4 * 64, 1, AsH, AsL, BsH, BsL);
    gbar();
    // G5: feat = U2 @ Ws2b + bs2b  [256,256] K=256
    if (bid < 16) dgemm64(g_U2, Ws2b, bs2b, g_feat, LL, LL, ty4 * 64, tx4 * 64, 2, AsH, AsL, BsH, BsL);
    gbar();
    // G6: Q3 = feat @ Wc1a  [256,512] K=256
    dgemm64(g_feat, Wc1a, (const float*)0, g_Q3, HH, LL, ty8 * 64, tx8 * 64, 0, AsH, AsL, BsH, BsL);
    gbar();
    // G7: U3 = relu(B @ Q3 + bc1a)  [256,512] K=256
    dgemm64(g_B, g_Q3, bc1a, g_U3, HH, NN, ty8 * 64, tx8 * 64, 1, AsH, AsL, BsH, BsL);
    gbar();
    // G8: s = relu(U3 @ Wc1b + bc1b)  [256,512] K=512
    dgemm64(g_U3, Wc1b, bc1b, g_s, HH, HH, ty8 * 64, tx8 * 64, 1, AsH, AsL, BsH, BsL);
    gbar();

    // ---- q4 + dementia partials ----
    #pragma unroll
    for (int rr = 0; rr < 2; rr++) {
        int row = bid * 4 + wid + rr * 128;
        float s = 0.f;
        for (int i = lane; i < HH; i += 32) s += g_s[row * HH + i] * Wc2a[i];
        #pragma unroll
        for (int o = 16; o; o >>= 1) s += __shfl_down_sync(0xFFFFFFFFu, s, o);
        if (lane == 0) g_Q4[row] = s;
    }
    {
        float ds = 0.f;
        int base = bid * 2048;
        for (int i = t; i < 2048; i += 128) ds += g_feat[base + i] * Wd[base + i];
        #pragma unroll
        for (int o = 16; o; o >>= 1) ds += __shfl_down_sync(0xFFFFFFFFu, ds, o);
        if (lane == 0) dred[wid] = ds;
        __syncthreads();
        if (t == 0) g_dpart[bid] = dred[0] + dred[1] + dred[2] + dred[3];
    }
    gbar();

    // ---- region scores + dementia combine ----
    #pragma unroll
    for (int rr = 0; rr < 2; rr++) {
        int row = bid * 4 + wid + rr * 128;
        float s = 0.f;
        for (int i = lane; i < NN; i += 32) s += g_B[row * NN + i] * g_Q4[i];
        #pragma unroll
        for (int o = 16; o; o >>= 1) s += __shfl_down_sync(0xFFFFFFFFu, s, o);
        if (lane == 0) {
            float u = fmaxf(s + bc2a[0], 0.f);
            float sc = u * Wc2b[0] + bc2b[0];
            out[1 + row] = 1.f / (1.f + expf(-sc));
        }
    }
    if (bid == 0 && wid == 0) {
        float v = g_dpart[lane];
        #pragma unroll
        for (int o = 16; o; o >>= 1) v += __shfl_down_sync(0xFFFFFFFFu, v, o);
        if (lane == 0) out[0] = 1.f / (1.f + expf(-(v + bd[0])));
    }
}

// ---------------- launch ----------------
extern "C" void kernel_launch(void* const* d_in, const int* in_sizes, int n_in,
                              void* d_out, int out_size) {
    const float* X    = (const float*)d_in[0];
    const int*   idx  = (const int*)d_in[1];
    const float* Ws1a = (const float*)d_in[3];
    const float* bs1a = (const float*)d_in[4];
    const float* Ws1b = (const float*)d_in[5];
    const float* bs1b = (const float*)d_in[6];
    const float* Ws2a = (const float*)d_in[7];
    const float* bs2a = (const float*)d_in[8];
    const float* Ws2b = (const float*)d_in[9];
    const float* bs2b = (const float*)d_in[10];
    const float* Wc1a = (const float*)d_in[11];
    const float* bc1a = (const float*)d_in[12];
    const float* Wc1b = (const float*)d_in[13];
    const float* bc1b = (const float*)d_in[14];
    const float* Wc2a = (const float*)d_in[15];
    const float* bc2a = (const float*)d_in[16];
    const float* Wc2b = (const float*)d_in[17];
    const float* bc2b = (const float*)d_in[18];
    const float* Wd   = (const float*)d_in[19];
    const float* bd   = (const float*)d_in[20];
    float* out = (float*)d_out;

    float* pPpart;
    __nv_bfloat16 *pXh, *pXl, *pWh, *pWl;
    cudaGetSymbolAddress((void**)&pPpart, g_Ppart);
    cudaGetSymbolAddress((void**)&pXh, g_Xh);
    cudaGetSymbolAddress((void**)&pXl, g_Xl);
    cudaGetSymbolAddress((void**)&pWh, g_Wh);
    cudaGetSymbolAddress((void**)&pWl, g_Wl);

    cudaFuncSetAttribute(bigmm3, cudaFuncAttributeMaxDynamicSharedMemorySize, SMEM_DYN);

    k_cvt<<<(NN * TT / 8 + 255) / 256, 256>>>(X, pXh, pXl, NN * TT / 8);
    k_cvt<<<(TT * HH / 8 + 255) / 256, 256>>>(Ws1a, pWh, pWl, TT * HH / 8);
    bigmm3<<<dim3(4, 2, SPLITKZ), 256, SMEM_DYN>>>(pPpart);
    k_chain<<<NCTA, 128>>>(idx, bs1a, Ws1b, bs1b, Ws2a, bs2a, Ws2b, bs2b,
                           Wc1a, bc1a, Wc1b, bc1b, Wc2a, bc2a, Wc2b, bc2b,
                           Wd, bd, out);
}

// round 7
// speedup vs baseline: 3.6020x; 1.2112x over previous
#include <cuda_runtime.h>
#include <cuda_bf16.h>
#include <math.h>

#define NN 256
#define TT 30000
#define HH 512
#define LL 256
#define EE 32768

#define KSTEPS 1875        // 30000/16
#define SPLITKZ 37
#define SPG 51

// bigmm smem stage layout (bytes)
#define ASTRIDE 24
#define BSTRIDE 136
#define ST_AH 0
#define ST_AL 6144
#define ST_BH 12288
#define ST_BL 16640
#define STAGE 20992
#define NSTAGE 4
#define SMEM_DYN (STAGE * NSTAGE)

// small gemm strides
#define SASTR 24
#define SBSTR 72
// chain smem layout (bytes within s_all)
#define CH_AH 0
#define CH_AL 12288
#define CH_BH 24576
#define CH_BL 33792
#define CH_TOT 43008

#define NCTA 32

// ---------------- device scratch ----------------
__device__ float g_B[NN * NN];
__device__ __nv_bfloat16 g_Xh[NN * TT], g_Xl[NN * TT];
__device__ __nv_bfloat16 g_Wh[TT * HH], g_Wl[TT * HH];
__device__ float g_Ppart[SPLITKZ * NN * HH];
__device__ float g_P[NN * HH];
__device__ float g_U1[NN * HH];
__device__ float g_h[NN * HH];
__device__ float g_Q2[NN * LL];
__device__ float g_U2[NN * LL];
__device__ float g_feat[NN * LL];
__device__ float g_Q3[NN * HH];
__device__ float g_U3[NN * HH];
__device__ float g_s[NN * HH];
__device__ float g_Q4[NN];
__device__ float g_dpart[NCTA];
__device__ unsigned g_bar_cnt;
__device__ unsigned g_bar_gen;

// ---------------- fused fp32 -> bf16 hi/lo split (X and W) ----------------
__global__ void k_cvt2(const float* __restrict__ X, const float* __restrict__ W) {
    const int nX = NN * TT / 8, nW = TT * HH / 8;
    int i = blockIdx.x * blockDim.x + threadIdx.x;
    const float* src; __nv_bfloat16 *hi, *lo; int j8;
    if (i < nX) { src = X; hi = g_Xh; lo = g_Xl; j8 = i; }
    else if (i < nX + nW) { src = W; hi = g_Wh; lo = g_Wl; j8 = i - nX; }
    else return;
    float4 v0 = ((const float4*)src)[2 * j8], v1 = ((const float4*)src)[2 * j8 + 1];
    float f[8] = {v0.x, v0.y, v0.z, v0.w, v1.x, v1.y, v1.z, v1.w};
    union { __nv_bfloat16 b[8]; uint4 u; } H, L;
    #pragma unroll
    for (int j = 0; j < 8; j++) {
        __nv_bfloat16 h = __float2bfloat16(f[j]);
        H.b[j] = h; L.b[j] = __float2bfloat16(f[j] - __bfloat162float(h));
    }
    ((uint4*)hi)[j8] = H.u;
    ((uint4*)lo)[j8] = L.u;
}

// ---------------- PTX helpers ----------------
__device__ __forceinline__ void mma_bf16(float* c, const unsigned* a, const unsigned* b) {
    asm volatile(
        "mma.sync.aligned.m16n8k16.row.col.f32.bf16.bf16.f32 "
        "{%0,%1,%2,%3},{%4,%5,%6,%7},{%8,%9},{%0,%1,%2,%3};"
        : "+f"(c[0]), "+f"(c[1]), "+f"(c[2]), "+f"(c[3])
        : "r"(a[0]), "r"(a[1]), "r"(a[2]), "r"(a[3]), "r"(b[0]), "r"(b[1]));
}
__device__ __forceinline__ void ldsm4(unsigned* r, unsigned addr) {
    asm volatile("ldmatrix.sync.aligned.m8n8.x4.shared.b16 {%0,%1,%2,%3},[%4];"
                 : "=r"(r[0]), "=r"(r[1]), "=r"(r[2]), "=r"(r[3]) : "r"(addr));
}
__device__ __forceinline__ void ldsm4t(unsigned* r, unsigned addr) {
    asm volatile("ldmatrix.sync.aligned.m8n8.x4.trans.shared.b16 {%0,%1,%2,%3},[%4];"
                 : "=r"(r[0]), "=r"(r[1]), "=r"(r[2]), "=r"(r[3]) : "r"(addr));
}
__device__ __forceinline__ void cpa16(unsigned dst, const void* src) {
    asm volatile("cp.async.cg.shared.global [%0], [%1], 16;" :: "r"(dst), "l"(src));
}
__device__ __forceinline__ void cpa_commit() { asm volatile("cp.async.commit_group;"); }
template <int N> __device__ __forceinline__ void cpa_wait() {
    asm volatile("cp.async.wait_group %0;" :: "n"(N));
}

// ---------------- big GEMM (unchanged) ----------------
__global__ __launch_bounds__(256, 2)
void bigmm3(float* __restrict__ Ppart)
{
    extern __shared__ char dyn[];
    const unsigned sb = (unsigned)__cvta_generic_to_shared(dyn);

    const int t = threadIdx.x;
    const int m0 = blockIdx.y * 128, n0 = blockIdx.x * 128, z = blockIdx.z;
    const int s0 = z * SPG;
    const int ns = min(SPG, KSTEPS - s0);

    const int arow = t >> 1, ach = t & 1;
    const int brow = t >> 4, bch = t & 15;
    const __nv_bfloat16* gAh = g_Xh + (size_t)(m0 + arow) * TT + (size_t)s0 * 16 + ach * 8;
    const __nv_bfloat16* gAl = g_Xl + (size_t)(m0 + arow) * TT + (size_t)s0 * 16 + ach * 8;
    const __nv_bfloat16* gBh = g_Wh + (size_t)((size_t)s0 * 16 + brow) * HH + n0 + bch * 8;
    const __nv_bfloat16* gBl = g_Wl + (size_t)((size_t)s0 * 16 + brow) * HH + n0 + bch * 8;
    const unsigned dA = arow * 48 + ach * 16;
    const unsigned dB = brow * 272 + bch * 16;

    const int lane = t & 31, wid = t >> 5;
    const int wm = wid & 3, wn = wid >> 2;
    unsigned offA[2], offB[4];
    {
        int r = lane & 15, c = (lane >> 4) * 8;
        offA[0] = ((wm * 32 + r) * ASTRIDE + c) * 2;
        offA[1] = ((wm * 32 + 16 + r) * ASTRIDE + c) * 2;
        int br = (lane & 7) + ((lane & 16) ? 8 : 0);
        int bc = (lane & 8) ? 8 : 0;
        #pragma unroll
        for (int p = 0; p < 4; p++)
            offB[p] = (br * BSTRIDE + wn * 64 + p * 16 + bc) * 2;
    }

    float acc[2][8][4];
    #pragma unroll
    for (int i = 0; i < 2; i++)
        #pragma unroll
        for (int j = 0; j < 8; j++)
            #pragma unroll
            for (int q = 0; q < 4; q++) acc[i][j][q] = 0.f;

    #pragma unroll
    for (int sg = 0; sg < NSTAGE - 1; sg++) {
        if (sg < ns) {
            unsigned base = sb + sg * STAGE;
            cpa16(base + ST_AH + dA, gAh + sg * 16);
            cpa16(base + ST_AL + dA, gAl + sg * 16);
            cpa16(base + ST_BH + dB, gBh + (size_t)sg * 16 * HH);
            cpa16(base + ST_BL + dB, gBl + (size_t)sg * 16 * HH);
        }
        cpa_commit();
    }

    for (int s = 0; s < ns; s++) {
        cpa_wait<NSTAGE - 2>();
        __syncthreads();

        int sg = s + NSTAGE - 1;
        if (sg < ns) {
            unsigned base = sb + (sg & (NSTAGE - 1)) * STAGE;
            cpa16(base + ST_AH + dA, gAh + (size_t)sg * 16);
            cpa16(base + ST_AL + dA, gAl + (size_t)sg * 16);
            cpa16(base + ST_BH + dB, gBh + (size_t)sg * 16 * HH);
            cpa16(base + ST_BL + dB, gBl + (size_t)sg * 16 * HH);
        }
        cpa_commit();

        const unsigned base = sb + (s & (NSTAGE - 1)) * STAGE;
        unsigned aH[2][4], aL[2][4];
        ldsm4(aH[0], base + ST_AH + offA[0]);
        ldsm4(aH[1], base + ST_AH + offA[1]);
        ldsm4(aL[0], base + ST_AL + offA[0]);
        ldsm4(aL[1], base + ST_AL + offA[1]);
        #pragma unroll
        for (int p = 0; p < 4; p++) {
            unsigned r[4], q[4];
            ldsm4t(r, base + ST_BH + offB[p]);
            ldsm4t(q, base + ST_BL + offB[p]);
            unsigned bh0[2] = {r[0], r[2]}, bh1[2] = {r[1], r[3]};
            unsigned bl0[2] = {q[0], q[2]}, bl1[2] = {q[1], q[3]};
            #pragma unroll
            for (int mi = 0; mi < 2; mi++) {
                mma_bf16(acc[mi][2 * p],     aH[mi], bh0);
                mma_bf16(acc[mi][2 * p],     aH[mi], bl0);
                mma_bf16(acc[mi][2 * p],     aL[mi], bh0);
                mma_bf16(acc[mi][2 * p + 1], aH[mi], bh1);
                mma_bf16(acc[mi][2 * p + 1], aH[mi], bl1);
                mma_bf16(acc[mi][2 * p + 1], aL[mi], bh1);
            }
        }
    }

    float* Po = Ppart + (size_t)z * NN * HH;
    #pragma unroll
    for (int mi = 0; mi < 2; mi++) {
        int row = m0 + wm * 32 + mi * 16 + (lane >> 2);
        #pragma unroll
        for (int ni = 0; ni < 8; ni++) {
            int col = n0 + wn * 64 + ni * 8 + (lane & 3) * 2;
            *(float2*)&Po[(size_t)row * HH + col]       = make_float2(acc[mi][ni][0], acc[mi][ni][1]);
            *(float2*)&Po[(size_t)(row + 8) * HH + col] = make_float2(acc[mi][ni][2], acc[mi][ni][3]);
        }
    }
}

// ---------------- device-wide barrier ----------------
__device__ __forceinline__ void gbar() {
    __syncthreads();
    if (threadIdx.x == 0) {
        __threadfence();
        unsigned old = *(volatile unsigned*)&g_bar_gen;
        unsigned a = atomicAdd(&g_bar_cnt, 1u);
        if (a == NCTA - 1) {
            g_bar_cnt = 0;
            __threadfence();
            *(volatile unsigned*)&g_bar_gen = old + 1;
        } else {
            while (*(volatile unsigned*)&g_bar_gen == old) __nanosleep(64);
        }
        __threadfence();
    }
    __syncthreads();
}

// ---------------- 64x64 tile GEMM, warp-split-K, 256 threads ----------------
__device__ void dgemm64(const float* __restrict__ A, const float* __restrict__ Bm,
                        const float* __restrict__ bias, float* __restrict__ C,
                        int N, int K, int m0, int n0, int epi, int aexact,
                        unsigned char* sm)
{
    __nv_bfloat16* AsH = (__nv_bfloat16*)(sm + CH_AH);
    __nv_bfloat16* AsL = (__nv_bfloat16*)(sm + CH_AL);
    __nv_bfloat16* BsH = (__nv_bfloat16*)(sm + CH_BH);
    __nv_bfloat16* BsL = (__nv_bfloat16*)(sm + CH_BL);

    const int t = threadIdx.x;
    const int kg = t >> 7;            // K-group 0/1
    const int t7 = t & 127;
    const int Kh = K >> 1;
    const int ns = Kh >> 4;

    const int arow = t7 >> 1, ak = (t7 & 1) * 8;
    const int brow = t7 >> 3, bn = (t7 & 7) * 8;
    const float* gA = A + (size_t)(m0 + arow) * K + kg * Kh + ak;
    const float* gB = Bm + (size_t)(kg * Kh + brow) * N + n0 + bn;

    const int lane = t & 31;
    const int wid2 = (t >> 5) & 3;
    const int wm = wid2 & 1, wn = wid2 >> 1;

    const int aBase = kg * 2 * 64 * SASTR;
    const int bBase = kg * 2 * 16 * SBSTR;
    const unsigned sAH = (unsigned)__cvta_generic_to_shared(AsH + aBase);
    const unsigned sAL = (unsigned)__cvta_generic_to_shared(AsL + aBase);
    const unsigned sBH = (unsigned)__cvta_generic_to_shared(BsH + bBase);
    const unsigned sBL = (unsigned)__cvta_generic_to_shared(BsL + bBase);

    unsigned offA[2], offB[2];
    {
        int r = lane & 15, c = (lane >> 4) * 8;
        offA[0] = ((wm * 32 + r) * SASTR + c) * 2;
        offA[1] = ((wm * 32 + 16 + r) * SASTR + c) * 2;
        int br = (lane & 7) + ((lane & 16) ? 8 : 0);
        int bc = (lane & 8) ? 8 : 0;
        offB[0] = (br * SBSTR + wn * 32 + bc) * 2;
        offB[1] = (br * SBSTR + wn * 32 + 16 + bc) * 2;
    }

    float fa[8], fb[8];
    float acc[2][4][4];
    #pragma unroll
    for (int i = 0; i < 2; i++)
        #pragma unroll
        for (int j = 0; j < 4; j++)
            #pragma unroll
            for (int q = 0; q < 4; q++) acc[i][j][q] = 0.f;

    // prologue: stage step 0
    {
        float4 v0 = *(const float4*)gA, v1 = *(const float4*)(gA + 4);
        fa[0]=v0.x; fa[1]=v0.y; fa[2]=v0.z; fa[3]=v0.w; fa[4]=v1.x; fa[5]=v1.y; fa[6]=v1.z; fa[7]=v1.w;
        float4 w0 = *(const float4*)gB, w1 = *(const float4*)(gB + 4);
        fb[0]=w0.x; fb[1]=w0.y; fb[2]=w0.z; fb[3]=w0.w; fb[4]=w1.x; fb[5]=w1.y; fb[6]=w1.z; fb[7]=w1.w;
        union { __nv_bfloat16 b[8]; uint4 u; } ph, pl;
        #pragma unroll
        for (int j = 0; j < 8; j++) {
            __nv_bfloat16 h = __float2bfloat16(fa[j]);
            ph.b[j] = h; pl.b[j] = __float2bfloat16(fa[j] - __bfloat162float(h));
        }
        *(uint4*)&AsH[aBase + arow * SASTR + ak] = ph.u;
        if (!aexact) *(uint4*)&AsL[aBase + arow * SASTR + ak] = pl.u;
        #pragma unroll
        for (int j = 0; j < 8; j++) {
            __nv_bfloat16 h = __float2bfloat16(fb[j]);
            ph.b[j] = h; pl.b[j] = __float2bfloat16(fb[j] - __bfloat162float(h));
        }
        *(uint4*)&BsH[bBase + brow * SBSTR + bn] = ph.u;
        *(uint4*)&BsL[bBase + brow * SBSTR + bn] = pl.u;
    }
    __syncthreads();

    for (int s = 0; s < ns; s++) {
        const int buf = s & 1;
        if (s + 1 < ns) {
            const float* pa = gA + (size_t)(s + 1) * 16;
            float4 v0 = *(const float4*)pa, v1 = *(const float4*)(pa + 4);
            fa[0]=v0.x; fa[1]=v0.y; fa[2]=v0.z; fa[3]=v0.w; fa[4]=v1.x; fa[5]=v1.y; fa[6]=v1.z; fa[7]=v1.w;
            const float* pb = gB + (size_t)(s + 1) * 16 * N;
            float4 w0 = *(const float4*)pb, w1 = *(const float4*)(pb + 4);
            fb[0]=w0.x; fb[1]=w0.y; fb[2]=w0.z; fb[3]=w0.w; fb[4]=w1.x; fb[5]=w1.y; fb[6]=w1.z; fb[7]=w1.w;
        }

        {
            const unsigned aOff = (unsigned)(buf * 64 * SASTR * 2);
            const unsigned bOff = (unsigned)(buf * 16 * SBSTR * 2);
            unsigned aH[2][4], aL[2][4];
            ldsm4(aH[0], sAH + aOff + offA[0]);
            ldsm4(aH[1], sAH + aOff + offA[1]);
            if (!aexact) {
                ldsm4(aL[0], sAL + aOff + offA[0]);
                ldsm4(aL[1], sAL + aOff + offA[1]);
            }
            unsigned bH[4][2], bL[4][2];
            #pragma unroll
            for (int p = 0; p < 2; p++) {
                unsigned r[4];
                ldsm4t(r, sBH + bOff + offB[p]);
                bH[2*p][0] = r[0]; bH[2*p][1] = r[2]; bH[2*p+1][0] = r[1]; bH[2*p+1][1] = r[3];
                ldsm4t(r, sBL + bOff + offB[p]);
                bL[2*p][0] = r[0]; bL[2*p][1] = r[2]; bL[2*p+1][0] = r[1]; bL[2*p+1][1] = r[3];
            }
            #pragma unroll
            for (int mi = 0; mi < 2; mi++)
                #pragma unroll
                for (int ni = 0; ni < 4; ni++) {
                    mma_bf16(acc[mi][ni], aH[mi], bH[ni]);
                    mma_bf16(acc[mi][ni], aH[mi], bL[ni]);
                }
            if (!aexact) {
                #pragma unroll
                for (int mi = 0; mi < 2; mi++)
                    #pragma unroll
                    for (int ni = 0; ni < 4; ni++)
                        mma_bf16(acc[mi][ni], aL[mi], bH[ni]);
            }
        }

        if (s + 1 < ns) {
            const int nb = buf ^ 1;
            union { __nv_bfloat16 b[8]; uint4 u; } ph, pl;
            #pragma unroll
            for (int j = 0; j < 8; j++) {
                __nv_bfloat16 h = __float2bfloat16(fa[j]);
                ph.b[j] = h; pl.b[j] = __float2bfloat16(fa[j] - __bfloat162float(h));
            }
            *(uint4*)&AsH[aBase + nb * 64 * SASTR + arow * SASTR + ak] = ph.u;
            if (!aexact) *(uint4*)&AsL[aBase + nb * 64 * SASTR + arow * SASTR + ak] = pl.u;
            #pragma unroll
            for (int j = 0; j < 8; j++) {
                __nv_bfloat16 h = __float2bfloat16(fb[j]);
                ph.b[j] = h; pl.b[j] = __float2bfloat16(fb[j] - __bfloat162float(h));
            }
            *(uint4*)&BsH[bBase + nb * 16 * SBSTR + brow * SBSTR + bn] = ph.u;
            *(uint4*)&BsL[bBase + nb * 16 * SBSTR + brow * SBSTR + bn] = pl.u;
        }
        __syncthreads();
    }

    // combine the two K-groups through smem (padded stride 33, conflict-free)
    float* comb = (float*)(sm + CH_BH);
    if (kg == 1) {
        int base = t7 * 33;
        #pragma unroll
        for (int mi = 0; mi < 2; mi++)
            #pragma unroll
            for (int ni = 0; ni < 4; ni++)
                #pragma unroll
                for (int q = 0; q < 4; q++)
                    comb[base + mi * 16 + ni * 4 + q] = acc[mi][ni][q];
    }
    __syncthreads();
    if (kg == 0) {
        int base = t7 * 33;
        #pragma unroll
        for (int mi = 0; mi < 2; mi++) {
            int row = m0 + wm * 32 + mi * 16 + (lane >> 2);
            #pragma unroll
            for (int ni = 0; ni < 4; ni++) {
                int col = n0 + wn * 32 + ni * 8 + (lane & 3) * 2;
                float v[4];
                #pragma unroll
                for (int q = 0; q < 4; q++)
                    v[q] = acc[mi][ni][q] + comb[base + mi * 16 + ni * 4 + q];
                if (epi) {
                    float2 b = *(const float2*)&bias[col];
                    v[0] += b.x; v[1] += b.y; v[2] += b.x; v[3] += b.y;
                }
                if (epi == 1) {
                    v[0] = fmaxf(v[0], 0.f); v[1] = fmaxf(v[1], 0.f);
                    v[2] = fmaxf(v[2], 0.f); v[3] = fmaxf(v[3], 0.f);
                }
                *(float2*)&C[(size_t)row * N + col]       = make_float2(v[0], v[1]);
                *(float2*)&C[(size_t)(row + 8) * N + col] = make_float2(v[2], v[3]);
            }
        }
    }
    __syncthreads();
}

// ---------------- persistent chain kernel (256 threads) ----------------
__global__ __launch_bounds__(256)
void k_chain(const int* __restrict__ idx,
             const float* __restrict__ bs1a, const float* __restrict__ Ws1b, const float* __restrict__ bs1b,
             const float* __restrict__ Ws2a, const float* __restrict__ bs2a,
             const float* __restrict__ Ws2b, const float* __restrict__ bs2b,
             const float* __restrict__ Wc1a, const float* __restrict__ bc1a,
             const float* __restrict__ Wc1b, const float* __restrict__ bc1b,
             const float* __restrict__ Wc2a, const float* __restrict__ bc2a,
             const float* __restrict__ Wc2b, const float* __restrict__ bc2b,
             const float* __restrict__ Wd, const float* __restrict__ bd,
             float* __restrict__ out)
{
    static __shared__ __align__(16) unsigned char s_all[CH_TOT];
    __shared__ float dred[8];

    const int bid = blockIdx.x, t = threadIdx.x;
    const int gid = bid * 256 + t;              // 0..8191
    const int wid = t >> 5, lane = t & 31;

    // ---- phase 0a: B identity init + reduceP ----
    #pragma unroll
    for (int j = 0; j < 2; j++) {
        int i4 = gid + j * 8192;                // 16384 float4
        int e0 = i4 * 4;
        float4 v = make_float4(0.f, 0.f, 0.f, 0.f);
        float* pv = &v.x;
        #pragma unroll
        for (int q = 0; q < 4; q++) {
            int e = e0 + q;
            if ((e >> 8) == (e & 255)) pv[q] = 1.f;
        }
        ((float4*)g_B)[i4] = v;
    }
    #pragma unroll
    for (int j = 0; j < 4; j++) {
        int i = gid + j * 8192;                 // 32768 float4
        float4 s = make_float4(0.f, 0.f, 0.f, 0.f);
        #pragma unroll
        for (int z = 0; z < SPLITKZ; z++) {
            float4 v = ((const float4*)g_Ppart)[(size_t)z * (NN * HH / 4) + i];
            s.x += v.x; s.y += v.y; s.z += v.z; s.w += v.w;
        }
        ((float4*)g_P)[i] = s;
    }
    gbar();

    // ---- phase 0b: edge atomics ----
    #pragma unroll
    for (int j = 0; j < 4; j++) {
        int e = gid + j * 8192;
        atomicAdd(&g_B[idx[EE + e] * NN + idx[e]], 1.0f);
    }
    gbar();

    const int tx8 = bid & 7, ty8 = bid >> 3;
    const int tx4 = bid & 3, ty4 = bid >> 2;

    // G1: U1 = relu(B @ P + bs1a)   K=256, A exact
    dgemm64(g_B, g_P, bs1a, g_U1, HH, NN, ty8 * 64, tx8 * 64, 1, 1, s_all);
    gbar();
    // G2: h = relu(U1 @ Ws1b + bs1b)  K=512
    dgemm64(g_U1, Ws1b, bs1b, g_h, HH, HH, ty8 * 64, tx8 * 64, 1, 0, s_all);
    gbar();
    // G3: Q2 = h @ Ws2a   K=512
    if (bid < 16) dgemm64(g_h, Ws2a, (const float*)0, g_Q2, LL, HH, ty4 * 64, tx4 * 64, 0, 0, s_all);
    gbar();
    // G4: U2 = relu(B @ Q2 + bs2a)  K=256, A exact
    if (bid < 16) dgemm64(g_B, g_Q2, bs2a, g_U2, LL, NN, ty4 * 64, tx4 * 64, 1, 1, s_all);
    gbar();
    // G5: feat = U2 @ Ws2b + bs2b   K=256
    if (bid < 16) dgemm64(g_U2, Ws2b, bs2b, g_feat, LL, LL, ty4 * 64, tx4 * 64, 2, 0, s_all);
    gbar();
    // G6: Q3 = feat @ Wc1a   K=256
    dgemm64(g_feat, Wc1a, (const float*)0, g_Q3, HH, LL, ty8 * 64, tx8 * 64, 0, 0, s_all);
    gbar();
    // G7: U3 = relu(B @ Q3 + bc1a)  K=256, A exact
    dgemm64(g_B, g_Q3, bc1a, g_U3, HH, NN, ty8 * 64, tx8 * 64, 1, 1, s_all);
    gbar();
    // G8: s = relu(U3 @ Wc1b + bc1b)  K=512
    dgemm64(g_U3, Wc1b, bc1b, g_s, HH, HH, ty8 * 64, tx8 * 64, 1, 0, s_all);
    gbar();

    // ---- q4 + dementia partials ----
    {
        int row = bid * 8 + wid;                // 256 rows
        float s = 0.f;
        for (int i = lane; i < HH; i += 32) s += g_s[row * HH + i] * Wc2a[i];
        #pragma unroll
        for (int o = 16; o; o >>= 1) s += __shfl_down_sync(0xFFFFFFFFu, s, o);
        if (lane == 0) g_Q4[row] = s;
    }
    {
        float ds = 0.f;
        int base = bid * 2048;
        for (int i = t; i < 2048; i += 256) ds += g_feat[base + i] * Wd[base + i];
        #pragma unroll
        for (int o = 16; o; o >>= 1) ds += __shfl_down_sync(0xFFFFFFFFu, ds, o);
        if (lane == 0) dred[wid] = ds;
        __syncthreads();
        if (t == 0) {
            float v = 0.f;
            #pragma unroll
            for (int j = 0; j < 8; j++) v += dred[j];
            g_dpart[bid] = v;
        }
    }
    gbar();

    // ---- region scores + dementia combine ----
    {
        int row = bid * 8 + wid;
        float s = 0.f;
        for (int i = lane; i < NN; i += 32) s += g_B[row * NN + i] * g_Q4[i];
        #pragma unroll
        for (int o = 16; o; o >>= 1) s += __shfl_down_sync(0xFFFFFFFFu, s, o);
        if (lane == 0) {
            float u = fmaxf(s + bc2a[0], 0.f);
            float sc = u * Wc2b[0] + bc2b[0];
            out[1 + row] = 1.f / (1.f + expf(-sc));
        }
    }
    if (bid == 0 && wid == 0) {
        float v = g_dpart[lane];
        #pragma unroll
        for (int o = 16; o; o >>= 1) v += __shfl_down_sync(0xFFFFFFFFu, v, o);
        if (lane == 0) out[0] = 1.f / (1.f + expf(-(v + bd[0])));
    }
}

// ---------------- launch ----------------
extern "C" void kernel_launch(void* const* d_in, const int* in_sizes, int n_in,
                              void* d_out, int out_size) {
    const float* X    = (const float*)d_in[0];
    const int*   idx  = (const int*)d_in[1];
    const float* Ws1a = (const float*)d_in[3];
    const float* bs1a = (const float*)d_in[4];
    const float* Ws1b = (const float*)d_in[5];
    const float* bs1b = (const float*)d_in[6];
    const float* Ws2a = (const float*)d_in[7];
    const float* bs2a = (const float*)d_in[8];
    const float* Ws2b = (const float*)d_in[9];
    const float* bs2b = (const float*)d_in[10];
    const float* Wc1a = (const float*)d_in[11];
    const float* bc1a = (const float*)d_in[12];
    const float* Wc1b = (const float*)d_in[13];
    const float* bc1b = (const float*)d_in[14];
    const float* Wc2a = (const float*)d_in[15];
    const float* bc2a = (const float*)d_in[16];
    const float* Wc2b = (const float*)d_in[17];
    const float* bc2b = (const float*)d_in[18];
    const float* Wd   = (const float*)d_in[19];
    const float* bd   = (const float*)d_in[20];
    float* out = (float*)d_out;

    float* pPpart;
    cudaGetSymbolAddress((void**)&pPpart, g_Ppart);

    cudaFuncSetAttribute(bigmm3, cudaFuncAttributeMaxDynamicSharedMemorySize, SMEM_DYN);

    const int nCvt = NN * TT / 8 + TT * HH / 8;
    k_cvt2<<<(nCvt + 255) / 256, 256>>>(X, Ws1a);
    bigmm3<<<dim3(4, 2, SPLITKZ), 256, SMEM_DYN>>>(pPpart);
    k_chain<<<NCTA, 256>>>(idx, bs1a, Ws1b, bs1b, Ws2a, bs2a, Ws2b, bs2b,
                           Wc1a, bc1a, Wc1b, bc1b, Wc2a, bc2a, Wc2b, bc2b,
                           Wd, bd, out);
}